// round 10
// baseline (speedup 1.0000x reference)
#include <cuda_runtime.h>
#include <math.h>

// ---------------------------------------------------------------------------
// Problem constants
// ---------------------------------------------------------------------------
#define BATCH 8
#define NH 8
#define SEQ 512
#define DIM 512
#define HD 64
#define USZ ((long)BATCH * SEQ * DIM)       // 2097152 floats per stream buffer
#define KA_PAD 208                          // a-modality K padded to 16

// ---------------------------------------------------------------------------
// Scratch (device globals; no allocations allowed)
// ---------------------------------------------------------------------------
__device__ float g_U[3 * 2097152];          // unified l,v,a
__device__ float g_qA[9 * 2097152];         // layer-0 outputs per stream
__device__ float g_qB[9 * 2097152];         // layer-1 outputs per stream
__device__ float g_ctx[9 * 2097152];        // ctx; also prologue pad scratch
__device__ float g_tmp[9 * 2097152];
__device__ float g_W[18 * DIM * DIM];       // proj @ minus_bottom
__device__ float g_sum[6 * BATCH * DIM];
__device__ float g_max[6 * BATCH * DIM];

// ---------------------------------------------------------------------------
// MMA / cp.async helpers
// ---------------------------------------------------------------------------
#define MMA_TF32(d, a, b)                                                     \
    asm volatile(                                                             \
        "mma.sync.aligned.m16n8k8.row.col.f32.tf32.tf32.f32 "                 \
        "{%0,%1,%2,%3},{%4,%5,%6,%7},{%8,%9},{%0,%1,%2,%3};"                  \
        : "+f"(d[0]), "+f"(d[1]), "+f"(d[2]), "+f"(d[3])                      \
        : "r"(a[0]), "r"(a[1]), "r"(a[2]), "r"(a[3]), "r"(b[0]), "r"(b[1]))

__device__ __forceinline__ void cp16(unsigned dst, const float* src)
{
    asm volatile("cp.async.cg.shared.global [%0], [%1], 16;"
                 :: "r"(dst), "l"(src));
}

// stream tables: qsrc[s] = s/3 ; kvi[s] via 2-bit packed code {0,1,2,1,0,2,2,0,1}
__device__ __forceinline__ int kvi_of(int s) { return (75876 >> (2 * s)) & 3; }

// ---------------------------------------------------------------------------
// Shared GEMM body (verified): NN, CTA tile 128x64x16, cp.async 3-stage.
// K%16==0, lda%4==0, 16B-aligned ptrs. SPLIT: k >= Ksplit reads A2/B2.
// ---------------------------------------------------------------------------
template<bool SPLIT>
__device__ __forceinline__ void gemm_body(
    const float* __restrict__ A, const float* __restrict__ A2,
    const float* __restrict__ B, const float* __restrict__ B2,
    int Ksplit, float* __restrict__ C,
    int K, int lda, int ldb, int ldc)
{
    __shared__ float As[3][128 * 20];
    __shared__ float Bs[3][1280];

    const int tid = threadIdx.x;
    const int bm = blockIdx.y * 128;
    const int bn = blockIdx.x * 64;
    const int warp = tid >> 5;
    const int warpm = warp & 3, warpn = warp >> 2;
    const int lane = tid & 31;
    const int lr = lane >> 2, lc = lane & 3;
    const int nT = K >> 4;

    const int ar = tid >> 2;
    const int aj = (tid & 3) << 2;
    const long aoff0 = (long)(bm + ar) * lda + aj;
    const long aoff1 = (long)(bm + ar + 64) * lda + aj;
    const long boffg = (long)(tid >> 4) * ldb + bn + ((tid & 15) << 2);

    const unsigned asb = (unsigned)__cvta_generic_to_shared(As);
    const unsigned bsb = (unsigned)__cvta_generic_to_shared(Bs);
    const unsigned sa0 = asb + (unsigned)(ar * 20 + aj) * 4u;
    const unsigned sa1 = asb + (unsigned)((ar + 64) * 20 + aj) * 4u;
    const unsigned sb0 = bsb + (unsigned)((tid >> 4) * 72 + ((tid & 15) << 2)) * 4u;

    auto load_tile = [&](int t, int st) {
        int k0 = t << 4;
        const float* Ab = A; const float* Bb = B; int kk = k0;
        if (SPLIT && k0 >= Ksplit) { Ab = A2; Bb = B2; kk = k0 - Ksplit; }
        unsigned oa = (unsigned)st * (128 * 20 * 4u);
        unsigned ob = (unsigned)st * (1280 * 4u);
        cp16(sa0 + oa, Ab + aoff0 + kk);
        cp16(sa1 + oa, Ab + aoff1 + kk);
        cp16(sb0 + ob, Bb + (long)kk * ldb + boffg);
    };

#pragma unroll
    for (int st = 0; st < 2; st++) {
        if (st < nT) load_tile(st, st);
        asm volatile("cp.async.commit_group;");
    }

    float acc[2][4][4] = {};
    const int afb = (warpm * 32 + lr) * 20 + lc;
    const int bfb = lc * 72 + warpn * 32 + lr;

    for (int t = 0; t < nT; t++) {
        asm volatile("cp.async.wait_group 1;");
        __syncthreads();
        if (t + 2 < nT) load_tile(t + 2, (t + 2) % 3);
        asm volatile("cp.async.commit_group;");

        const float* as = As[t % 3];
        const float* bs = Bs[t % 3];
#pragma unroll
        for (int ks = 0; ks < 2; ks++) {
            unsigned af[2][4];
#pragma unroll
            for (int mi = 0; mi < 2; mi++) {
                int base = afb + mi * 320 + ks * 8;
                af[mi][0] = __float_as_uint(as[base]);
                af[mi][1] = __float_as_uint(as[base + 160]);
                af[mi][2] = __float_as_uint(as[base + 4]);
                af[mi][3] = __float_as_uint(as[base + 164]);
            }
            unsigned bf[4][2];
#pragma unroll
            for (int ni = 0; ni < 4; ni++) {
                int base = bfb + ni * 8 + ks * 576;
                bf[ni][0] = __float_as_uint(bs[base]);
                bf[ni][1] = __float_as_uint(bs[base + 288]);
            }
#pragma unroll
            for (int mi = 0; mi < 2; mi++)
#pragma unroll
                for (int ni = 0; ni < 4; ni++)
                    MMA_TF32(acc[mi][ni], af[mi], bf[ni]);
        }
    }

#pragma unroll
    for (int mi = 0; mi < 2; mi++)
#pragma unroll
        for (int ni = 0; ni < 4; ni++) {
            int row0 = bm + warpm * 32 + mi * 16 + lr;
            int col = bn + warpn * 32 + ni * 8 + lc * 2;
#pragma unroll
            for (int rr = 0; rr < 2; rr++) {
                int row = row0 + rr * 8;
                *(float2*)&C[(long)row * ldc + col] =
                    make_float2(acc[mi][ni][rr * 2], acc[mi][ni][rr * 2 + 1]);
            }
        }
}

// plain batched wrapper (W precompute)
__global__ void __launch_bounds__(256, 2) tc_plain(
    const float* __restrict__ A, const float* __restrict__ B,
    float* __restrict__ C, int K, int lda, int ldb, int ldc,
    long sA, long sB, long sC)
{
    int z = blockIdx.z;
    gemm_body<false>(A + z * sA, nullptr, B + z * sB, nullptr, 0,
                     C + z * sC, K, lda, ldb, ldc);
}

// batched unify: z=0 l(K=768), z=1 v(K=640), z=2 padded-a(K=208)
__global__ void __launch_bounds__(256, 2) unify_b(
    const float* __restrict__ l, const float* __restrict__ v,
    const float* __restrict__ pa,
    const float* __restrict__ wl, const float* __restrict__ wv,
    const float* __restrict__ pwa, float* __restrict__ tmpb)
{
    int z = blockIdx.z;
    const float* A; const float* B; int K;
    if (z == 0)      { A = l;  B = wl;  K = 768; }
    else if (z == 1) { A = v;  B = wv;  K = 640; }
    else             { A = pa; B = pwa; K = KA_PAD; }
    gemm_body<false>(A, nullptr, B, nullptr, 0,
                     tmpb + (long)z * USZ, K, K, DIM, DIM);
}

// batched minus GEMM: tmp[s] = qin[s] @ minus_top[i] + ctx[s] @ W[i], i=s*2+L
template<int LAYER>
__global__ void __launch_bounds__(256, 2) minus_b(
    const float* __restrict__ Ub, const float* __restrict__ Qprev,
    const float* __restrict__ ctxb, const float* __restrict__ minus_w,
    const float* __restrict__ Wb, float* __restrict__ tmpb)
{
    int s = blockIdx.z;
    const float* A = (LAYER == 0) ? Ub + (s / 3) * USZ : Qprev + s * USZ;
    int i = s * 2 + LAYER;
    gemm_body<true>(A, ctxb + s * USZ,
                    minus_w + (long)i * 2 * DIM * DIM,
                    Wb + (long)i * DIM * DIM,
                    DIM, tmpb + s * USZ, 2 * DIM, DIM, DIM, DIM);
}

// pad a [4096,205]->[4096,208] and wa [205,512]->[208,512] (zero fill)
__global__ void pad_a_kernel(
    const float* __restrict__ a, const float* __restrict__ wa,
    float* __restrict__ pa, float* __restrict__ pwa)
{
    int idx = blockIdx.x * 256 + threadIdx.x;
    const int NA = 4096 * KA_PAD;            // 851968
    const int NB = KA_PAD * DIM;             // 106496
    if (idx < NA) {
        int r = idx / KA_PAD, c = idx - r * KA_PAD;
        pa[idx] = (c < 205) ? a[r * 205 + c] : 0.f;
    } else if (idx < NA + NB) {
        int j = idx - NA;
        int r = j >> 9, c = j & 511;
        pwa[j] = (r < 205) ? wa[r * DIM + c] : 0.f;
    }
}

// ---------------------------------------------------------------------------
// Persistent-K fused attention (verified round-9): one CTA per z (grid 576).
// ---------------------------------------------------------------------------
#define L2E 1.44269504f

template<int LAYER>
__global__ void __launch_bounds__(256, 1) attn_fused(
    const float* __restrict__ Ub, const float* __restrict__ Qprev,
    float* __restrict__ ctxb,
    const float* __restrict__ m0, const float* __restrict__ m1,
    const float* __restrict__ m2, const float* __restrict__ cvec)
{
    extern __shared__ float sm[];
    float* Ks   = sm;                  // 512*68
    float* Qs   = Ks + 512 * 68;       // 32*68
    float* Ps   = Qs + 32 * 68;        // 32*516 (also ctx partial buffer 8*2048)
    float* red  = Ps + 32 * 516;       // 8*32
    float* rmax = red + 256;           // 32
    float* rinv = rmax + 32;           // 32

    const int z = blockIdx.x;
    const int s = z >> 6;
    const int bb = (z >> 3) & 7;
    const int hh = z & 7;

    const int tid = threadIdx.x;
    const int w = tid >> 5;
    const int lane = tid & 31;
    const int lr = lane >> 2, lc = lane & 3;

    const int kv = kvi_of(s);
    const float* q0p = Ub + (s / 3) * USZ;
    const float* qin = (LAYER == 0) ? q0p : Qprev + s * USZ;
    const float* kvp = Ub + kv * USZ;
    const float* maskp = ((kv == 0) ? m0 : (kv == 1) ? m1 : m2) + bb * SEQ;

    const float* Qg  = qin + (long)bb * SEQ * DIM + hh * HD;
    const float* Q0g = q0p + (long)bb * SEQ * DIM + hh * HD;
    const float* Kg  = kvp + (long)bb * SEQ * DIM + hh * HD;

    const float SCL = 0.125f * L2E;    // scores scale in log2 domain
    float cv = 0.f, pscale = 1e8f * L2E;
    if (LAYER == 1) { cv = cvec[s * 2 + 1]; pscale = (1.f + cv) * 1e8f * L2E; }

    // ---- stage K (512x64), resident for whole CTA ----
    {
        unsigned ksb = (unsigned)__cvta_generic_to_shared(Ks);
        int r = tid >> 4, c = (tid & 15) << 2;
#pragma unroll
        for (int i = 0; i < 32; i++) {
            int rr = r + i * 16;
            cp16(ksb + (unsigned)(rr * 68 + c) * 4u, Kg + (long)rr * DIM + c);
        }
        asm volatile("cp.async.commit_group;");
        asm volatile("cp.async.wait_group 0;");
    }
    __syncthreads();

    // mask penalties for this warp's score columns (reused across q-tiles)
    const int nbase = w * 64;
    float mpen[8][2];
#pragma unroll
    for (int ni = 0; ni < 8; ni++) {
        mpen[ni][0] = pscale * (1.f - maskp[nbase + ni * 8 + lc * 2]);
        mpen[ni][1] = pscale * (1.f - maskp[nbase + ni * 8 + lc * 2 + 1]);
    }

    for (int qt = 0; qt < 16; qt++) {
        const int row0 = qt * 32;

        // ---- stage Q tile (32x64); layer 1 stages Qeff = Q1 + c*Q0 ----
        if (LAYER == 0) {
            unsigned qsb = (unsigned)__cvta_generic_to_shared(Qs);
#pragma unroll
            for (int i = 0; i < 2; i++) {
                int idx = tid + i * 256;
                int qr = idx >> 4, qc = (idx & 15) << 2;
                cp16(qsb + (unsigned)(qr * 68 + qc) * 4u,
                     Qg + (long)(row0 + qr) * DIM + qc);
            }
            asm volatile("cp.async.commit_group;");
            asm volatile("cp.async.wait_group 0;");
        } else {
#pragma unroll
            for (int i = 0; i < 8; i++) {
                int idx = tid + i * 256;
                int qr = idx >> 6, qc = idx & 63;
                long go = (long)(row0 + qr) * DIM + qc;
                Qs[qr * 68 + qc] = Qg[go] + cv * Q0g[go];
            }
        }
        __syncthreads();   // Qs ready; fences prev iteration's Ps/rinv reads

        // ---- scores: warp w owns seq cols [w*64, w*64+64) ----
        float acc[2][8][4] = {};
#pragma unroll
        for (int ks = 0; ks < 8; ks++) {
            unsigned af[2][4];
#pragma unroll
            for (int mi = 0; mi < 2; mi++) {
                const float* q = &Qs[(mi * 16 + lr) * 68 + ks * 8 + lc];
                af[mi][0] = __float_as_uint(q[0]);
                af[mi][1] = __float_as_uint(q[8 * 68]);
                af[mi][2] = __float_as_uint(q[4]);
                af[mi][3] = __float_as_uint(q[8 * 68 + 4]);
            }
#pragma unroll
            for (int ni = 0; ni < 8; ni++) {
                unsigned bf[2];
                const float* kp = &Ks[(nbase + ni * 8 + lr) * 68 + ks * 8 + lc];
                bf[0] = __float_as_uint(kp[0]);
                bf[1] = __float_as_uint(kp[4]);
#pragma unroll
                for (int mi = 0; mi < 2; mi++)
                    MMA_TF32(acc[mi][ni], af[mi], bf);
            }
        }

        // ---- scale (log2 domain) + mask ----
#pragma unroll
        for (int mi = 0; mi < 2; mi++)
#pragma unroll
            for (int ni = 0; ni < 8; ni++) {
                acc[mi][ni][0] = acc[mi][ni][0] * SCL - mpen[ni][0];
                acc[mi][ni][1] = acc[mi][ni][1] * SCL - mpen[ni][1];
                acc[mi][ni][2] = acc[mi][ni][2] * SCL - mpen[ni][0];
                acc[mi][ni][3] = acc[mi][ni][3] * SCL - mpen[ni][1];
            }

        // ---- softmax: row max ----
        float lred[4];
#pragma unroll
        for (int i = 0; i < 4; i++) {
            int mi = i >> 1, rr = i & 1;
            float m = -INFINITY;
#pragma unroll
            for (int ni = 0; ni < 8; ni++)
                m = fmaxf(m, fmaxf(acc[mi][ni][rr * 2], acc[mi][ni][rr * 2 + 1]));
            m = fmaxf(m, __shfl_xor_sync(0xffffffffu, m, 1));
            m = fmaxf(m, __shfl_xor_sync(0xffffffffu, m, 2));
            lred[i] = m;
        }
        if (lc == 0)
#pragma unroll
            for (int i = 0; i < 4; i++)
                red[w * 32 + (i >> 1) * 16 + (i & 1) * 8 + lr] = lred[i];
        __syncthreads();
        if (tid < 32) {
            float m = red[tid];
#pragma unroll
            for (int ww = 1; ww < 8; ww++) m = fmaxf(m, red[ww * 32 + tid]);
            rmax[tid] = m;
        }
        __syncthreads();

        // ---- exp2 -> Ps (unnormalized), row sum ----
#pragma unroll
        for (int i = 0; i < 4; i++) {
            int mi = i >> 1, rr = i & 1;
            int row = mi * 16 + rr * 8 + lr;
            float rm = rmax[row];
            float* prow = &Ps[row * 516 + nbase + lc * 2];
            float sum = 0.f;
#pragma unroll
            for (int ni = 0; ni < 8; ni++) {
                float e0 = exp2f(acc[mi][ni][rr * 2] - rm);
                float e1 = exp2f(acc[mi][ni][rr * 2 + 1] - rm);
                prow[ni * 8] = e0; prow[ni * 8 + 1] = e1;
                sum += e0 + e1;
            }
            sum += __shfl_xor_sync(0xffffffffu, sum, 1);
            sum += __shfl_xor_sync(0xffffffffu, sum, 2);
            lred[i] = sum;
        }
        if (lc == 0)
#pragma unroll
            for (int i = 0; i < 4; i++)
                red[w * 32 + (i >> 1) * 16 + (i & 1) * 8 + lr] = lred[i];
        __syncthreads();
        if (tid < 32) {
            float sum = 0.f;
#pragma unroll
            for (int ww = 0; ww < 8; ww++) sum += red[ww * 32 + tid];
            rinv[tid] = 1.f / sum;
        }
        __syncthreads();

        // ---- ctx partials: warp w takes k-slice [w*64,w*64+64), all 64 cols
        float cacc[2][8][4] = {};
#pragma unroll
        for (int ks = 0; ks < 8; ks++) {
            const int kg = w * 64 + ks * 8;
            unsigned af[2][4];
#pragma unroll
            for (int mi = 0; mi < 2; mi++) {
                const float* p = &Ps[(mi * 16 + lr) * 516 + kg + lc];
                af[mi][0] = __float_as_uint(p[0]);
                af[mi][1] = __float_as_uint(p[8 * 516]);
                af[mi][2] = __float_as_uint(p[4]);
                af[mi][3] = __float_as_uint(p[8 * 516 + 4]);
            }
#pragma unroll
            for (int ni = 0; ni < 8; ni++) {
                unsigned bf[2];
                const float* kp = &Ks[(kg + lc) * 68 + ni * 8 + lr];
                bf[0] = __float_as_uint(kp[0]);
                bf[1] = __float_as_uint(kp[4 * 68]);
#pragma unroll
                for (int mi = 0; mi < 2; mi++)
                    MMA_TF32(cacc[mi][ni], af[mi], bf);
            }
        }
        __syncthreads();   // all Ps reads complete before overlay

        // store partials into Ps region, per-row rotated units (no conflicts)
        {
            float* pb = Ps + w * 2048;
#pragma unroll
            for (int mi = 0; mi < 2; mi++)
#pragma unroll
                for (int rr = 0; rr < 2; rr++) {
                    int row = mi * 16 + rr * 8 + lr;
#pragma unroll
                    for (int ni = 0; ni < 8; ni++) {
                        int u = (ni * 4 + lc + row * 4) & 31;
                        *(float2*)&pb[row * 64 + u * 2] =
                            make_float2(cacc[mi][ni][rr * 2],
                                        cacc[mi][ni][rr * 2 + 1]);
                    }
                }
        }
        __syncthreads();

        // reduce 8 partials, scale by rinv, store ctx (coalesced float2)
        float* ctxg = ctxb + (long)s * USZ + (long)bb * SEQ * DIM
                    + (long)row0 * DIM + hh * HD;
#pragma unroll
        for (int i = 0; i < 4; i++) {
            int idx = tid + i * 256;       // float2 unit over 32x32 units
            int row = idx >> 5;
            int u = idx & 31;
            int up = (u + row * 4) & 31;
            float sx = 0.f, sy = 0.f;
#pragma unroll
            for (int ww = 0; ww < 8; ww++) {
                float2 vv = *(float2*)&Ps[ww * 2048 + row * 64 + up * 2];
                sx += vv.x; sy += vv.y;
            }
            float inv = rinv[row];
            *(float2*)&ctxg[(long)row * DIM + u * 2] =
                make_float2(sx * inv, sy * inv);
        }
        // next iteration's first __syncthreads orders Ps reuse
    }
}

// ---------------------------------------------------------------------------
// LayerNorm (warp-shuffle reductions). param offset = (row >> 12) * pstride.
// ---------------------------------------------------------------------------
__global__ void __launch_bounds__(256) ln_all(
    const float* __restrict__ X, float* __restrict__ Y,
    const float* __restrict__ g, const float* __restrict__ b, int pstride)
{
    long row = blockIdx.x;
    int pi = (int)(row >> 12);
    g += (long)pi * pstride;
    b += (long)pi * pstride;
    const float* x = X + row * DIM;
    float* y = Y + row * DIM;
    int tid = threadIdx.x;
    float v0 = x[tid], v1 = x[tid + 256];

    __shared__ float ws[8];
    __shared__ float bc[2];

    float sum = v0 + v1;
#pragma unroll
    for (int o = 16; o > 0; o >>= 1) sum += __shfl_xor_sync(0xffffffffu, sum, o);
    if ((tid & 31) == 0) ws[tid >> 5] = sum;
    __syncthreads();
    if (tid == 0) {
        float t = 0.f;
#pragma unroll
        for (int i = 0; i < 8; i++) t += ws[i];
        bc[0] = t * (1.f / DIM);
    }
    __syncthreads();
    float mu = bc[0];

    float d0 = v0 - mu, d1 = v1 - mu;
    float q = d0 * d0 + d1 * d1;
#pragma unroll
    for (int o = 16; o > 0; o >>= 1) q += __shfl_xor_sync(0xffffffffu, q, o);
    if ((tid & 31) == 0) ws[tid >> 5] = q;
    __syncthreads();
    if (tid == 0) {
        float t = 0.f;
#pragma unroll
        for (int i = 0; i < 8; i++) t += ws[i];
        bc[1] = rsqrtf(t * (1.f / DIM) + 1e-5f);
    }
    __syncthreads();
    float rstd = bc[1];

    y[tid] = d0 * rstd * g[tid] + b[tid];
    y[tid + 256] = d1 * rstd * g[tid + 256] + b[tid + 256];
}

// ---------------------------------------------------------------------------
// Pooling
// ---------------------------------------------------------------------------
__global__ void pool_init(float* s, float* m, int n)
{
    int i = blockIdx.x * blockDim.x + threadIdx.x;
    if (i < n) { s[i] = 0.f; m[i] = -INFINITY; }
}

__device__ __forceinline__ void atomicMaxF(float* addr, float val)
{
    int old = __float_as_int(*addr);
    while (__int_as_float(old) < val) {
        int assumed = old;
        old = atomicCAS((int*)addr, assumed, __float_as_int(val));
        if (old == assumed) break;
    }
}

// grid (16, 3 slots, 4 row-chunks); slot g <- streams {g, g+3, g+6}
__global__ void __launch_bounds__(256) pool_b(
    const float* __restrict__ Qb, float* __restrict__ sum,
    float* __restrict__ mx, int layer)
{
    int idx = blockIdx.x * 256 + threadIdx.x;   // (b,d)
    int bb = idx >> 9, d = idx & 511;
    int g = blockIdx.y;
    int r0 = blockIdx.z * 128;
    float s = 0.f, m = -INFINITY;
#pragma unroll
    for (int t = 0; t < 3; t++) {
        const float* p = Qb + (long)(g + t * 3) * USZ
                       + (long)bb * SEQ * DIM + (long)r0 * DIM + d;
        for (int r = 0; r < 128; r++) {
            float v = p[(long)r * DIM];
            s += v;
            m = fmaxf(m, v);
        }
    }
    int k = g * 2 + layer;
    atomicAdd(&sum[k * 4096 + idx], s);
    atomicMaxF(&mx[k * 4096 + idx], m);
}

// ---------------------------------------------------------------------------
// Classifier
// ---------------------------------------------------------------------------
__global__ void __launch_bounds__(256) clf_kernel(
    const float* __restrict__ sum, const float* __restrict__ mx,
    const float* __restrict__ W, float* __restrict__ out)
{
    int bb = blockIdx.x / 9, cls = blockIdx.x % 9;
    int tid = threadIdx.x;
    float acc = 0.f;
    for (int j = tid; j < 3072; j += 256) {
        int k = j >> 9, d = j & 511;
        float sm = sum[k * 4096 + bb * 512 + d] * (1.f / 1536.f);
        float mv = mx[k * 4096 + bb * 512 + d];
        acc += sm * W[(long)j * 9 + cls] + mv * W[(long)(3072 + j) * 9 + cls];
    }
    __shared__ float red[256];
    red[tid] = acc;
    __syncthreads();
    for (int s = 128; s > 0; s >>= 1) {
        if (tid < s) red[tid] += red[tid + s];
        __syncthreads();
    }
    if (tid == 0) out[bb * 9 + cls] = red[0];
}

// ---------------------------------------------------------------------------
// Host orchestration (single stream; no stream/event creation allowed)
// ---------------------------------------------------------------------------
extern "C" void kernel_launch(void* const* d_in, const int* in_sizes, int n_in,
                              void* d_out, int out_size)
{
    const float* l      = (const float*)d_in[0];
    const float* v      = (const float*)d_in[1];
    const float* a      = (const float*)d_in[2];
    const float* l_mask = (const float*)d_in[3];
    const float* v_mask = (const float*)d_in[4];
    const float* a_mask = (const float*)d_in[5];
    const float* wl     = (const float*)d_in[6];
    const float* wv     = (const float*)d_in[7];
    const float* wa     = (const float*)d_in[8];
    const float* n1_g   = (const float*)d_in[9];
    const float* n1_b   = (const float*)d_in[10];
    const float* proj_w = (const float*)d_in[11];
    const float* minus_w= (const float*)d_in[12];
    const float* n2_g   = (const float*)d_in[13];
    const float* n2_b   = (const float*)d_in[14];
    const float* cvec   = (const float*)d_in[15];
    const float* clf_w  = (const float*)d_in[16];
    float* out          = (float*)d_out;

    float *pU, *pqA, *pqB, *pctx, *ptmp, *pW, *psum, *pmax;
    cudaGetSymbolAddress((void**)&pU, g_U);
    cudaGetSymbolAddress((void**)&pqA, g_qA);
    cudaGetSymbolAddress((void**)&pqB, g_qB);
    cudaGetSymbolAddress((void**)&pctx, g_ctx);
    cudaGetSymbolAddress((void**)&ptmp, g_tmp);
    cudaGetSymbolAddress((void**)&pW, g_W);
    cudaGetSymbolAddress((void**)&psum, g_sum);
    cudaGetSymbolAddress((void**)&pmax, g_max);

    // prologue pad scratch lives in g_ctx (free until attention)
    float* pad_a = pctx;
    float* pad_wa = pctx + 4096 * KA_PAD;

    const int SMEM_ATTN = (512 * 68 + 32 * 68 + 32 * 516 + 256 + 64) * 4;
    cudaFuncSetAttribute(attn_fused<0>,
        cudaFuncAttributeMaxDynamicSharedMemorySize, SMEM_ATTN);
    cudaFuncSetAttribute(attn_fused<1>,
        cudaFuncAttributeMaxDynamicSharedMemorySize, SMEM_ATTN);

    pool_init<<<96, 256>>>(psum, pmax, 6 * BATCH * DIM);

    // pad a + wa into scratch
    pad_a_kernel<<<3744, 256>>>(a, wa, pad_a, pad_wa);

    // W[i] = proj_w[i] @ minus_w[i][512:1024]  (batched over 18 blocks)
    tc_plain<<<dim3(8, 4, 18), 256>>>(
        proj_w, minus_w + (long)DIM * DIM, pW, DIM, DIM, DIM, DIM,
        (long)DIM * DIM, (long)2 * DIM * DIM, (long)DIM * DIM);

    // --- Unify (all 3 modalities in one launch) + one merged LN ---
    unify_b<<<dim3(8, 32, 3), 256>>>(l, v, pad_a, wl, wv, pad_wa, ptmp);
    ln_all<<<3 * 4096, 256>>>(ptmp, pU, n1_g, n1_b, 0);

    // --- layer 0 (all 9 streams batched) ---
    attn_fused<0><<<576, 256, SMEM_ATTN>>>(
        pU, nullptr, pctx, l_mask, v_mask, a_mask, cvec);
    minus_b<0><<<dim3(8, 32, 9), 256>>>(pU, nullptr, pctx, minus_w, pW, ptmp);
    ln_all<<<9 * 4096, 256>>>(ptmp, pqA, n2_g, n2_b, 2 * DIM);
    pool_b<<<dim3(16, 3, 4), 256>>>(pqA, psum, pmax, 0);

    // --- layer 1 ---
    attn_fused<1><<<576, 256, SMEM_ATTN>>>(
        pU, pqA, pctx, l_mask, v_mask, a_mask, cvec);
    minus_b<1><<<dim3(8, 32, 9), 256>>>(pU, pqA, pctx, minus_w, pW, ptmp);
    ln_all<<<9 * 4096, 256>>>(ptmp, pqB, n2_g + DIM, n2_b + DIM, 2 * DIM);
    pool_b<<<dim3(16, 3, 4), 256>>>(pqB, psum, pmax, 1);

    clf_kernel<<<BATCH * 9, 256>>>(psum, pmax, clf_w, out);
}

// round 11
// speedup vs baseline: 1.0328x; 1.0328x over previous
#include <cuda_runtime.h>
#include <math.h>

// ---------------------------------------------------------------------------
// Problem constants
// ---------------------------------------------------------------------------
#define BATCH 8
#define NH 8
#define SEQ 512
#define DIM 512
#define HD 64
#define USZ ((long)BATCH * SEQ * DIM)       // 2097152 floats per stream buffer
#define KA_PAD 208                          // a-modality K padded to 16

// gemm dynamic smem: As 3*128*20 + Bs 3*16*136 floats
#define GEMM_SMEM ((3 * 2560 + 3 * 2176) * 4)

// ---------------------------------------------------------------------------
// Scratch (device globals; no allocations allowed)
// ---------------------------------------------------------------------------
__device__ float g_U[3 * 2097152];          // unified l,v,a
__device__ float g_qA[9 * 2097152];         // layer-0 outputs per stream
__device__ float g_qB[9 * 2097152];         // layer-1 outputs per stream
__device__ float g_ctx[9 * 2097152];        // ctx; also prologue pad scratch
__device__ float g_tmp[9 * 2097152];
__device__ float g_W[18 * DIM * DIM];       // proj @ minus_bottom
__device__ float g_sum[6 * BATCH * DIM];
__device__ float g_max[6 * BATCH * DIM];

// ---------------------------------------------------------------------------
// MMA / cp.async helpers
// ---------------------------------------------------------------------------
#define MMA_TF32(d, a, b)                                                     \
    asm volatile(                                                             \
        "mma.sync.aligned.m16n8k8.row.col.f32.tf32.tf32.f32 "                 \
        "{%0,%1,%2,%3},{%4,%5,%6,%7},{%8,%9},{%0,%1,%2,%3};"                  \
        : "+f"(d[0]), "+f"(d[1]), "+f"(d[2]), "+f"(d[3])                      \
        : "r"(a[0]), "r"(a[1]), "r"(a[2]), "r"(a[3]), "r"(b[0]), "r"(b[1]))

__device__ __forceinline__ void cp16(unsigned dst, const float* src)
{
    asm volatile("cp.async.cg.shared.global [%0], [%1], 16;"
                 :: "r"(dst), "l"(src));
}

// stream tables: qsrc[s] = s/3 ; kvi[s] via 2-bit packed code {0,1,2,1,0,2,2,0,1}
__device__ __forceinline__ int kvi_of(int s) { return (75876 >> (2 * s)) & 3; }

// ---------------------------------------------------------------------------
// Shared GEMM body: NN, CTA tile 128x128x16, cp.async 3-stage (same pipeline
// structure as the verified 128x64 version; N doubled for issue efficiency).
// 8 warps: warpm 0..3 (32 rows), warpn 0..1 (64 cols); acc 2x8x4 per thread.
// K%16==0, lda%4==0, ldb%4==0, 16B-aligned ptrs. SPLIT: k>=Ksplit -> A2/B2.
// Dynamic smem: As[3][2560] (rows padded to 20), Bs[3][2176] ([16][136]).
// ---------------------------------------------------------------------------
template<bool SPLIT>
__device__ __forceinline__ void gemm_body(
    const float* __restrict__ A, const float* __restrict__ A2,
    const float* __restrict__ B, const float* __restrict__ B2,
    int Ksplit, float* __restrict__ C,
    int K, int lda, int ldb, int ldc, float* sm)
{
    float* As = sm;                 // 3 * 2560
    float* Bs = sm + 3 * 2560;      // 3 * 2176

    const int tid = threadIdx.x;
    const int bm = blockIdx.y * 128;
    const int bn = blockIdx.x * 128;
    const int warp = tid >> 5;
    const int warpm = warp & 3, warpn = warp >> 2;
    const int lane = tid & 31;
    const int lr = lane >> 2, lc = lane & 3;
    const int nT = K >> 4;

    // A staging: 128x16 = 2048 elems, 2 cp16/thread
    const int ar = tid >> 2;
    const int aj = (tid & 3) << 2;
    const long aoff0 = (long)(bm + ar) * lda + aj;
    const long aoff1 = (long)(bm + ar + 64) * lda + aj;
    // B staging: 16x128 = 2048 elems, 2 cp16/thread (row tid>>4, col8 (tid&15)*8)
    const long boffg = (long)(tid >> 4) * ldb + bn + ((tid & 15) << 3);

    const unsigned asb = (unsigned)__cvta_generic_to_shared(As);
    const unsigned bsb = (unsigned)__cvta_generic_to_shared(Bs);
    const unsigned sa0 = asb + (unsigned)(ar * 20 + aj) * 4u;
    const unsigned sa1 = asb + (unsigned)((ar + 64) * 20 + aj) * 4u;
    const unsigned sb0 = bsb + (unsigned)((tid >> 4) * 136 + ((tid & 15) << 3)) * 4u;

    auto load_tile = [&](int t, int st) {
        int k0 = t << 4;
        const float* Ab = A; const float* Bb = B; int kk = k0;
        if (SPLIT && k0 >= Ksplit) { Ab = A2; Bb = B2; kk = k0 - Ksplit; }
        unsigned oa = (unsigned)st * (2560 * 4u);
        unsigned ob = (unsigned)st * (2176 * 4u);
        cp16(sa0 + oa, Ab + aoff0 + kk);
        cp16(sa1 + oa, Ab + aoff1 + kk);
        const float* bp = Bb + (long)kk * ldb + boffg;
        cp16(sb0 + ob, bp);
        cp16(sb0 + ob + 16u, bp + 4);
    };

#pragma unroll
    for (int st = 0; st < 2; st++) {
        if (st < nT) load_tile(st, st);
        asm volatile("cp.async.commit_group;");
    }

    float acc[2][8][4] = {};
    const int afb = (warpm * 32 + lr) * 20 + lc;
    const int bfb = lc * 136 + warpn * 64 + lr;

    for (int t = 0; t < nT; t++) {
        asm volatile("cp.async.wait_group 1;");
        __syncthreads();
        if (t + 2 < nT) load_tile(t + 2, (t + 2) % 3);
        asm volatile("cp.async.commit_group;");

        const float* as = As + (t % 3) * 2560;
        const float* bs = Bs + (t % 3) * 2176;
#pragma unroll
        for (int ks = 0; ks < 2; ks++) {
            unsigned af[2][4];
#pragma unroll
            for (int mi = 0; mi < 2; mi++) {
                int base = afb + mi * 320 + ks * 8;
                af[mi][0] = __float_as_uint(as[base]);
                af[mi][1] = __float_as_uint(as[base + 160]);
                af[mi][2] = __float_as_uint(as[base + 4]);
                af[mi][3] = __float_as_uint(as[base + 164]);
            }
            unsigned bf[8][2];
#pragma unroll
            for (int ni = 0; ni < 8; ni++) {
                int base = bfb + ni * 8 + ks * 1088;
                bf[ni][0] = __float_as_uint(bs[base]);
                bf[ni][1] = __float_as_uint(bs[base + 544]);
            }
#pragma unroll
            for (int mi = 0; mi < 2; mi++)
#pragma unroll
                for (int ni = 0; ni < 8; ni++)
                    MMA_TF32(acc[mi][ni], af[mi], bf[ni]);
        }
    }

#pragma unroll
    for (int mi = 0; mi < 2; mi++)
#pragma unroll
        for (int ni = 0; ni < 8; ni++) {
            int row0 = bm + warpm * 32 + mi * 16 + lr;
            int col = bn + warpn * 64 + ni * 8 + lc * 2;
#pragma unroll
            for (int rr = 0; rr < 2; rr++) {
                int row = row0 + rr * 8;
                *(float2*)&C[(long)row * ldc + col] =
                    make_float2(acc[mi][ni][rr * 2], acc[mi][ni][rr * 2 + 1]);
            }
        }
}

// plain batched wrapper (W precompute)
__global__ void __launch_bounds__(256) tc_plain(
    const float* __restrict__ A, const float* __restrict__ B,
    float* __restrict__ C, int K, int lda, int ldb, int ldc,
    long sA, long sB, long sC)
{
    extern __shared__ float dynsm[];
    int z = blockIdx.z;
    gemm_body<false>(A + z * sA, nullptr, B + z * sB, nullptr, 0,
                     C + z * sC, K, lda, ldb, ldc, dynsm);
}

// batched unify: z=0 l(K=768), z=1 v(K=640), z=2 padded-a(K=208)
__global__ void __launch_bounds__(256) unify_b(
    const float* __restrict__ l, const float* __restrict__ v,
    const float* __restrict__ pa,
    const float* __restrict__ wl, const float* __restrict__ wv,
    const float* __restrict__ pwa, float* __restrict__ tmpb)
{
    extern __shared__ float dynsm[];
    int z = blockIdx.z;
    const float* A; const float* B; int K;
    if (z == 0)      { A = l;  B = wl;  K = 768; }
    else if (z == 1) { A = v;  B = wv;  K = 640; }
    else             { A = pa; B = pwa; K = KA_PAD; }
    gemm_body<false>(A, nullptr, B, nullptr, 0,
                     tmpb + (long)z * USZ, K, K, DIM, DIM, dynsm);
}

// batched minus GEMM: tmp[s] = qin[s] @ minus_top[i] + ctx[s] @ W[i], i=s*2+L
template<int LAYER>
__global__ void __launch_bounds__(256) minus_b(
    const float* __restrict__ Ub, const float* __restrict__ Qprev,
    const float* __restrict__ ctxb, const float* __restrict__ minus_w,
    const float* __restrict__ Wb, float* __restrict__ tmpb)
{
    extern __shared__ float dynsm[];
    int s = blockIdx.z;
    const float* A = (LAYER == 0) ? Ub + (s / 3) * USZ : Qprev + s * USZ;
    int i = s * 2 + LAYER;
    gemm_body<true>(A, ctxb + s * USZ,
                    minus_w + (long)i * 2 * DIM * DIM,
                    Wb + (long)i * DIM * DIM,
                    DIM, tmpb + s * USZ, 2 * DIM, DIM, DIM, DIM, dynsm);
}

// pad a [4096,205]->[4096,208] and wa [205,512]->[208,512] (zero fill)
__global__ void pad_a_kernel(
    const float* __restrict__ a, const float* __restrict__ wa,
    float* __restrict__ pa, float* __restrict__ pwa)
{
    int idx = blockIdx.x * 256 + threadIdx.x;
    const int NA = 4096 * KA_PAD;            // 851968
    const int NB = KA_PAD * DIM;             // 106496
    if (idx < NA) {
        int r = idx / KA_PAD, c = idx - r * KA_PAD;
        pa[idx] = (c < 205) ? a[r * 205 + c] : 0.f;
    } else if (idx < NA + NB) {
        int j = idx - NA;
        int r = j >> 9, c = j & 511;
        pwa[j] = (r < 205) ? wa[r * DIM + c] : 0.f;
    }
}

// ---------------------------------------------------------------------------
// Persistent-K fused attention (verified round-9): one CTA per z (grid 576).
// ---------------------------------------------------------------------------
#define L2E 1.44269504f

template<int LAYER>
__global__ void __launch_bounds__(256, 1) attn_fused(
    const float* __restrict__ Ub, const float* __restrict__ Qprev,
    float* __restrict__ ctxb,
    const float* __restrict__ m0, const float* __restrict__ m1,
    const float* __restrict__ m2, const float* __restrict__ cvec)
{
    extern __shared__ float sm[];
    float* Ks   = sm;                  // 512*68
    float* Qs   = Ks + 512 * 68;       // 32*68
    float* Ps   = Qs + 32 * 68;        // 32*516 (also ctx partial buffer 8*2048)
    float* red  = Ps + 32 * 516;       // 8*32
    float* rmax = red + 256;           // 32
    float* rinv = rmax + 32;           // 32

    const int z = blockIdx.x;
    const int s = z >> 6;
    const int bb = (z >> 3) & 7;
    const int hh = z & 7;

    const int tid = threadIdx.x;
    const int w = tid >> 5;
    const int lane = tid & 31;
    const int lr = lane >> 2, lc = lane & 3;

    const int kv = kvi_of(s);
    const float* q0p = Ub + (s / 3) * USZ;
    const float* qin = (LAYER == 0) ? q0p : Qprev + s * USZ;
    const float* kvp = Ub + kv * USZ;
    const float* maskp = ((kv == 0) ? m0 : (kv == 1) ? m1 : m2) + bb * SEQ;

    const float* Qg  = qin + (long)bb * SEQ * DIM + hh * HD;
    const float* Q0g = q0p + (long)bb * SEQ * DIM + hh * HD;
    const float* Kg  = kvp + (long)bb * SEQ * DIM + hh * HD;

    const float SCL = 0.125f * L2E;    // scores scale in log2 domain
    float cv = 0.f, pscale = 1e8f * L2E;
    if (LAYER == 1) { cv = cvec[s * 2 + 1]; pscale = (1.f + cv) * 1e8f * L2E; }

    // ---- stage K (512x64), resident for whole CTA ----
    {
        unsigned ksb = (unsigned)__cvta_generic_to_shared(Ks);
        int r = tid >> 4, c = (tid & 15) << 2;
#pragma unroll
        for (int i = 0; i < 32; i++) {
            int rr = r + i * 16;
            cp16(ksb + (unsigned)(rr * 68 + c) * 4u, Kg + (long)rr * DIM + c);
        }
        asm volatile("cp.async.commit_group;");
        asm volatile("cp.async.wait_group 0;");
    }
    __syncthreads();

    // mask penalties for this warp's score columns (reused across q-tiles)
    const int nbase = w * 64;
    float mpen[8][2];
#pragma unroll
    for (int ni = 0; ni < 8; ni++) {
        mpen[ni][0] = pscale * (1.f - maskp[nbase + ni * 8 + lc * 2]);
        mpen[ni][1] = pscale * (1.f - maskp[nbase + ni * 8 + lc * 2 + 1]);
    }

    for (int qt = 0; qt < 16; qt++) {
        const int row0 = qt * 32;

        // ---- stage Q tile (32x64); layer 1 stages Qeff = Q1 + c*Q0 ----
        if (LAYER == 0) {
            unsigned qsb = (unsigned)__cvta_generic_to_shared(Qs);
#pragma unroll
            for (int i = 0; i < 2; i++) {
                int idx = tid + i * 256;
                int qr = idx >> 4, qc = (idx & 15) << 2;
                cp16(qsb + (unsigned)(qr * 68 + qc) * 4u,
                     Qg + (long)(row0 + qr) * DIM + qc);
            }
            asm volatile("cp.async.commit_group;");
            asm volatile("cp.async.wait_group 0;");
        } else {
#pragma unroll
            for (int i = 0; i < 8; i++) {
                int idx = tid + i * 256;
                int qr = idx >> 6, qc = idx & 63;
                long go = (long)(row0 + qr) * DIM + qc;
                Qs[qr * 68 + qc] = Qg[go] + cv * Q0g[go];
            }
        }
        __syncthreads();   // Qs ready; fences prev iteration's Ps/rinv reads

        // ---- scores: warp w owns seq cols [w*64, w*64+64) ----
        float acc[2][8][4] = {};
#pragma unroll
        for (int ks = 0; ks < 8; ks++) {
            unsigned af[2][4];
#pragma unroll
            for (int mi = 0; mi < 2; mi++) {
                const float* q = &Qs[(mi * 16 + lr) * 68 + ks * 8 + lc];
                af[mi][0] = __float_as_uint(q[0]);
                af[mi][1] = __float_as_uint(q[8 * 68]);
                af[mi][2] = __float_as_uint(q[4]);
                af[mi][3] = __float_as_uint(q[8 * 68 + 4]);
            }
#pragma unroll
            for (int ni = 0; ni < 8; ni++) {
                unsigned bf[2];
                const float* kp = &Ks[(nbase + ni * 8 + lr) * 68 + ks * 8 + lc];
                bf[0] = __float_as_uint(kp[0]);
                bf[1] = __float_as_uint(kp[4]);
#pragma unroll
                for (int mi = 0; mi < 2; mi++)
                    MMA_TF32(acc[mi][ni], af[mi], bf);
            }
        }

        // ---- scale (log2 domain) + mask ----
#pragma unroll
        for (int mi = 0; mi < 2; mi++)
#pragma unroll
            for (int ni = 0; ni < 8; ni++) {
                acc[mi][ni][0] = acc[mi][ni][0] * SCL - mpen[ni][0];
                acc[mi][ni][1] = acc[mi][ni][1] * SCL - mpen[ni][1];
                acc[mi][ni][2] = acc[mi][ni][2] * SCL - mpen[ni][0];
                acc[mi][ni][3] = acc[mi][ni][3] * SCL - mpen[ni][1];
            }

        // ---- softmax: row max ----
        float lred[4];
#pragma unroll
        for (int i = 0; i < 4; i++) {
            int mi = i >> 1, rr = i & 1;
            float m = -INFINITY;
#pragma unroll
            for (int ni = 0; ni < 8; ni++)
                m = fmaxf(m, fmaxf(acc[mi][ni][rr * 2], acc[mi][ni][rr * 2 + 1]));
            m = fmaxf(m, __shfl_xor_sync(0xffffffffu, m, 1));
            m = fmaxf(m, __shfl_xor_sync(0xffffffffu, m, 2));
            lred[i] = m;
        }
        if (lc == 0)
#pragma unroll
            for (int i = 0; i < 4; i++)
                red[w * 32 + (i >> 1) * 16 + (i & 1) * 8 + lr] = lred[i];
        __syncthreads();
        if (tid < 32) {
            float m = red[tid];
#pragma unroll
            for (int ww = 1; ww < 8; ww++) m = fmaxf(m, red[ww * 32 + tid]);
            rmax[tid] = m;
        }
        __syncthreads();

        // ---- exp2 -> Ps (unnormalized), row sum ----
#pragma unroll
        for (int i = 0; i < 4; i++) {
            int mi = i >> 1, rr = i & 1;
            int row = mi * 16 + rr * 8 + lr;
            float rm = rmax[row];
            float* prow = &Ps[row * 516 + nbase + lc * 2];
            float sum = 0.f;
#pragma unroll
            for (int ni = 0; ni < 8; ni++) {
                float e0 = exp2f(acc[mi][ni][rr * 2] - rm);
                float e1 = exp2f(acc[mi][ni][rr * 2 + 1] - rm);
                prow[ni * 8] = e0; prow[ni * 8 + 1] = e1;
                sum += e0 + e1;
            }
            sum += __shfl_xor_sync(0xffffffffu, sum, 1);
            sum += __shfl_xor_sync(0xffffffffu, sum, 2);
            lred[i] = sum;
        }
        if (lc == 0)
#pragma unroll
            for (int i = 0; i < 4; i++)
                red[w * 32 + (i >> 1) * 16 + (i & 1) * 8 + lr] = lred[i];
        __syncthreads();
        if (tid < 32) {
            float sum = 0.f;
#pragma unroll
            for (int ww = 0; ww < 8; ww++) sum += red[ww * 32 + tid];
            rinv[tid] = 1.f / sum;
        }
        __syncthreads();

        // ---- ctx partials: warp w takes k-slice [w*64,w*64+64), all 64 cols
        float cacc[2][8][4] = {};
#pragma unroll
        for (int ks = 0; ks < 8; ks++) {
            const int kg = w * 64 + ks * 8;
            unsigned af[2][4];
#pragma unroll
            for (int mi = 0; mi < 2; mi++) {
                const float* p = &Ps[(mi * 16 + lr) * 516 + kg + lc];
                af[mi][0] = __float_as_uint(p[0]);
                af[mi][1] = __float_as_uint(p[8 * 516]);
                af[mi][2] = __float_as_uint(p[4]);
                af[mi][3] = __float_as_uint(p[8 * 516 + 4]);
            }
#pragma unroll
            for (int ni = 0; ni < 8; ni++) {
                unsigned bf[2];
                const float* kp = &Ks[(kg + lc) * 68 + ni * 8 + lr];
                bf[0] = __float_as_uint(kp[0]);
                bf[1] = __float_as_uint(kp[4 * 68]);
#pragma unroll
                for (int mi = 0; mi < 2; mi++)
                    MMA_TF32(cacc[mi][ni], af[mi], bf);
            }
        }
        __syncthreads();   // all Ps reads complete before overlay

        // store partials into Ps region, per-row rotated units (no conflicts)
        {
            float* pb = Ps + w * 2048;
#pragma unroll
            for (int mi = 0; mi < 2; mi++)
#pragma unroll
                for (int rr = 0; rr < 2; rr++) {
                    int row = mi * 16 + rr * 8 + lr;
#pragma unroll
                    for (int ni = 0; ni < 8; ni++) {
                        int u = (ni * 4 + lc + row * 4) & 31;
                        *(float2*)&pb[row * 64 + u * 2] =
                            make_float2(cacc[mi][ni][rr * 2],
                                        cacc[mi][ni][rr * 2 + 1]);
                    }
                }
        }
        __syncthreads();

        // reduce 8 partials, scale by rinv, store ctx (coalesced float2)
        float* ctxg = ctxb + (long)s * USZ + (long)bb * SEQ * DIM
                    + (long)row0 * DIM + hh * HD;
#pragma unroll
        for (int i = 0; i < 4; i++) {
            int idx = tid + i * 256;       // float2 unit over 32x32 units
            int row = idx >> 5;
            int u = idx & 31;
            int up = (u + row * 4) & 31;
            float sx = 0.f, sy = 0.f;
#pragma unroll
            for (int ww = 0; ww < 8; ww++) {
                float2 vv = *(float2*)&Ps[ww * 2048 + row * 64 + up * 2];
                sx += vv.x; sy += vv.y;
            }
            float inv = rinv[row];
            *(float2*)&ctxg[(long)row * DIM + u * 2] =
                make_float2(sx * inv, sy * inv);
        }
        // next iteration's first __syncthreads orders Ps reuse
    }
}

// ---------------------------------------------------------------------------
// LayerNorm (warp-shuffle reductions). param offset = (row >> 12) * pstride.
// ---------------------------------------------------------------------------
__global__ void __launch_bounds__(256) ln_all(
    const float* __restrict__ X, float* __restrict__ Y,
    const float* __restrict__ g, const float* __restrict__ b, int pstride)
{
    long row = blockIdx.x;
    int pi = (int)(row >> 12);
    g += (long)pi * pstride;
    b += (long)pi * pstride;
    const float* x = X + row * DIM;
    float* y = Y + row * DIM;
    int tid = threadIdx.x;
    float v0 = x[tid], v1 = x[tid + 256];

    __shared__ float ws[8];
    __shared__ float bc[2];

    float sum = v0 + v1;
#pragma unroll
    for (int o = 16; o > 0; o >>= 1) sum += __shfl_xor_sync(0xffffffffu, sum, o);
    if ((tid & 31) == 0) ws[tid >> 5] = sum;
    __syncthreads();
    if (tid == 0) {
        float t = 0.f;
#pragma unroll
        for (int i = 0; i < 8; i++) t += ws[i];
        bc[0] = t * (1.f / DIM);
    }
    __syncthreads();
    float mu = bc[0];

    float d0 = v0 - mu, d1 = v1 - mu;
    float q = d0 * d0 + d1 * d1;
#pragma unroll
    for (int o = 16; o > 0; o >>= 1) q += __shfl_xor_sync(0xffffffffu, q, o);
    if ((tid & 31) == 0) ws[tid >> 5] = q;
    __syncthreads();
    if (tid == 0) {
        float t = 0.f;
#pragma unroll
        for (int i = 0; i < 8; i++) t += ws[i];
        bc[1] = rsqrtf(t * (1.f / DIM) + 1e-5f);
    }
    __syncthreads();
    float rstd = bc[1];

    y[tid] = d0 * rstd * g[tid] + b[tid];
    y[tid + 256] = d1 * rstd * g[tid + 256] + b[tid + 256];
}

// ---------------------------------------------------------------------------
// Pooling
// ---------------------------------------------------------------------------
__global__ void pool_init(float* s, float* m, int n)
{
    int i = blockIdx.x * blockDim.x + threadIdx.x;
    if (i < n) { s[i] = 0.f; m[i] = -INFINITY; }
}

__device__ __forceinline__ void atomicMaxF(float* addr, float val)
{
    int old = __float_as_int(*addr);
    while (__int_as_float(old) < val) {
        int assumed = old;
        old = atomicCAS((int*)addr, assumed, __float_as_int(val));
        if (old == assumed) break;
    }
}

// grid (16, 3 slots, 4 row-chunks); slot g <- streams {g, g+3, g+6}
__global__ void __launch_bounds__(256) pool_b(
    const float* __restrict__ Qb, float* __restrict__ sum,
    float* __restrict__ mx, int layer)
{
    int idx = blockIdx.x * 256 + threadIdx.x;   // (b,d)
    int bb = idx >> 9, d = idx & 511;
    int g = blockIdx.y;
    int r0 = blockIdx.z * 128;
    float s = 0.f, m = -INFINITY;
#pragma unroll
    for (int t = 0; t < 3; t++) {
        const float* p = Qb + (long)(g + t * 3) * USZ
                       + (long)bb * SEQ * DIM + (long)r0 * DIM + d;
        for (int r = 0; r < 128; r++) {
            float v = p[(long)r * DIM];
            s += v;
            m = fmaxf(m, v);
        }
    }
    int k = g * 2 + layer;
    atomicAdd(&sum[k * 4096 + idx], s);
    atomicMaxF(&mx[k * 4096 + idx], m);
}

// ---------------------------------------------------------------------------
// Classifier
// ---------------------------------------------------------------------------
__global__ void __launch_bounds__(256) clf_kernel(
    const float* __restrict__ sum, const float* __restrict__ mx,
    const float* __restrict__ W, float* __restrict__ out)
{
    int bb = blockIdx.x / 9, cls = blockIdx.x % 9;
    int tid = threadIdx.x;
    float acc = 0.f;
    for (int j = tid; j < 3072; j += 256) {
        int k = j >> 9, d = j & 511;
        float sm = sum[k * 4096 + bb * 512 + d] * (1.f / 1536.f);
        float mv = mx[k * 4096 + bb * 512 + d];
        acc += sm * W[(long)j * 9 + cls] + mv * W[(long)(3072 + j) * 9 + cls];
    }
    __shared__ float red[256];
    red[tid] = acc;
    __syncthreads();
    for (int s = 128; s > 0; s >>= 1) {
        if (tid < s) red[tid] += red[tid + s];
        __syncthreads();
    }
    if (tid == 0) out[bb * 9 + cls] = red[0];
}

// ---------------------------------------------------------------------------
// Host orchestration (single stream; no stream/event creation allowed)
// ---------------------------------------------------------------------------
extern "C" void kernel_launch(void* const* d_in, const int* in_sizes, int n_in,
                              void* d_out, int out_size)
{
    const float* l      = (const float*)d_in[0];
    const float* v      = (const float*)d_in[1];
    const float* a      = (const float*)d_in[2];
    const float* l_mask = (const float*)d_in[3];
    const float* v_mask = (const float*)d_in[4];
    const float* a_mask = (const float*)d_in[5];
    const float* wl     = (const float*)d_in[6];
    const float* wv     = (const float*)d_in[7];
    const float* wa     = (const float*)d_in[8];
    const float* n1_g   = (const float*)d_in[9];
    const float* n1_b   = (const float*)d_in[10];
    const float* proj_w = (const float*)d_in[11];
    const float* minus_w= (const float*)d_in[12];
    const float* n2_g   = (const float*)d_in[13];
    const float* n2_b   = (const float*)d_in[14];
    const float* cvec   = (const float*)d_in[15];
    const float* clf_w  = (const float*)d_in[16];
    float* out          = (float*)d_out;

    float *pU, *pqA, *pqB, *pctx, *ptmp, *pW, *psum, *pmax;
    cudaGetSymbolAddress((void**)&pU, g_U);
    cudaGetSymbolAddress((void**)&pqA, g_qA);
    cudaGetSymbolAddress((void**)&pqB, g_qB);
    cudaGetSymbolAddress((void**)&pctx, g_ctx);
    cudaGetSymbolAddress((void**)&ptmp, g_tmp);
    cudaGetSymbolAddress((void**)&pW, g_W);
    cudaGetSymbolAddress((void**)&psum, g_sum);
    cudaGetSymbolAddress((void**)&pmax, g_max);

    // prologue pad scratch lives in g_ctx (free until attention)
    float* pad_a = pctx;
    float* pad_wa = pctx + 4096 * KA_PAD;

    const int SMEM_ATTN = (512 * 68 + 32 * 68 + 32 * 516 + 256 + 64) * 4;
    cudaFuncSetAttribute(attn_fused<0>,
        cudaFuncAttributeMaxDynamicSharedMemorySize, SMEM_ATTN);
    cudaFuncSetAttribute(attn_fused<1>,
        cudaFuncAttributeMaxDynamicSharedMemorySize, SMEM_ATTN);
    cudaFuncSetAttribute(tc_plain,
        cudaFuncAttributeMaxDynamicSharedMemorySize, GEMM_SMEM);
    cudaFuncSetAttribute(unify_b,
        cudaFuncAttributeMaxDynamicSharedMemorySize, GEMM_SMEM);
    cudaFuncSetAttribute(minus_b<0>,
        cudaFuncAttributeMaxDynamicSharedMemorySize, GEMM_SMEM);
    cudaFuncSetAttribute(minus_b<1>,
        cudaFuncAttributeMaxDynamicSharedMemorySize, GEMM_SMEM);

    pool_init<<<96, 256>>>(psum, pmax, 6 * BATCH * DIM);

    // pad a + wa into scratch
    pad_a_kernel<<<3744, 256>>>(a, wa, pad_a, pad_wa);

    // W[i] = proj_w[i] @ minus_w[i][512:1024]  (batched over 18 blocks)
    tc_plain<<<dim3(4, 4, 18), 256, GEMM_SMEM>>>(
        proj_w, minus_w + (long)DIM * DIM, pW, DIM, DIM, DIM, DIM,
        (long)DIM * DIM, (long)2 * DIM * DIM, (long)DIM * DIM);

    // --- Unify (all 3 modalities in one launch) + one merged LN ---
    unify_b<<<dim3(4, 32, 3), 256, GEMM_SMEM>>>(l, v, pad_a, wl, wv, pad_wa, ptmp);
    ln_all<<<3 * 4096, 256>>>(ptmp, pU, n1_g, n1_b, 0);

    // --- layer 0 (all 9 streams batched) ---
    attn_fused<0><<<576, 256, SMEM_ATTN>>>(
        pU, nullptr, pctx, l_mask, v_mask, a_mask, cvec);
    minus_b<0><<<dim3(4, 32, 9), 256, GEMM_SMEM>>>(
        pU, nullptr, pctx, minus_w, pW, ptmp);
    ln_all<<<9 * 4096, 256>>>(ptmp, pqA, n2_g, n2_b, 2 * DIM);
    pool_b<<<dim3(16, 3, 4), 256>>>(pqA, psum, pmax, 0);

    // --- layer 1 ---
    attn_fused<1><<<576, 256, SMEM_ATTN>>>(
        pU, pqA, pctx, l_mask, v_mask, a_mask, cvec);
    minus_b<1><<<dim3(4, 32, 9), 256, GEMM_SMEM>>>(
        pU, pqA, pctx, minus_w, pW, ptmp);
    ln_all<<<9 * 4096, 256>>>(ptmp, pqB, n2_g + DIM, n2_b + DIM, 2 * DIM);
    pool_b<<<dim3(16, 3, 4), 256>>>(pqB, psum, pmax, 1);

    clf_kernel<<<BATCH * 9, 256>>>(psum, pmax, clf_w, out);
}

// round 12
// speedup vs baseline: 1.0609x; 1.0273x over previous
#include <cuda_runtime.h>
#include <math.h>

// ---------------------------------------------------------------------------
// Problem constants
// ---------------------------------------------------------------------------
#define BATCH 8
#define NH 8
#define SEQ 512
#define DIM 512
#define HD 64
#define USZ ((long)BATCH * SEQ * DIM)       // 2097152 floats per stream buffer
#define KA_PAD 208                          // a-modality K padded to 16

// gemm dynamic smem: As 3*256*20 + Bs 3*16*136 floats = 87552 bytes
#define GEMM_SMEM ((3 * 5120 + 3 * 2176) * 4)

// ---------------------------------------------------------------------------
// Scratch (device globals; no allocations allowed)
// ---------------------------------------------------------------------------
__device__ float g_U[3 * 2097152];          // unified l,v,a
__device__ float g_qA[9 * 2097152];         // layer-0 outputs per stream
__device__ float g_qB[9 * 2097152];         // layer-1 outputs per stream
__device__ float g_ctx[9 * 2097152];        // ctx; also prologue pad scratch
__device__ float g_tmp[9 * 2097152];
__device__ float g_W[18 * DIM * DIM];       // proj @ minus_bottom
__device__ float g_sum[6 * BATCH * DIM];
__device__ float g_max[6 * BATCH * DIM];

// ---------------------------------------------------------------------------
// MMA / cp.async helpers
// ---------------------------------------------------------------------------
#define MMA_TF32(d, a, b)                                                     \
    asm volatile(                                                             \
        "mma.sync.aligned.m16n8k8.row.col.f32.tf32.tf32.f32 "                 \
        "{%0,%1,%2,%3},{%4,%5,%6,%7},{%8,%9},{%0,%1,%2,%3};"                  \
        : "+f"(d[0]), "+f"(d[1]), "+f"(d[2]), "+f"(d[3])                      \
        : "r"(a[0]), "r"(a[1]), "r"(a[2]), "r"(a[3]), "r"(b[0]), "r"(b[1]))

__device__ __forceinline__ void cp16(unsigned dst, const float* src)
{
    asm volatile("cp.async.cg.shared.global [%0], [%1], 16;"
                 :: "r"(dst), "l"(src));
}

// stream tables: qsrc[s] = s/3 ; kvi[s] via 2-bit packed code {0,1,2,1,0,2,2,0,1}
__device__ __forceinline__ int kvi_of(int s) { return (75876 >> (2 * s)) & 3; }

// ---------------------------------------------------------------------------
// Shared GEMM body: NN, CTA tile 256x128x16, cp.async 3-stage.
// 8 warps: warpm = warp&3 (64-row slabs), warpn = warp>>2 (64-col slabs).
// Warp tile 64x64 -> 64 LDS per 64 MMA per k-tile (1.0 ratio, vs 1.5 before).
// K%16==0, lda%4==0, ldb%4==0, 16B-aligned ptrs, M%256==0, N%128==0.
// SPLIT: k >= Ksplit reads A2/B2 (k rebased).
// Dynamic smem: As[3][5120] (256 rows padded to 20), Bs[3][2176] ([16][136]).
// ---------------------------------------------------------------------------
template<bool SPLIT>
__device__ __forceinline__ void gemm_body(
    const float* __restrict__ A, const float* __restrict__ A2,
    const float* __restrict__ B, const float* __restrict__ B2,
    int Ksplit, float* __restrict__ C,
    int K, int lda, int ldb, int ldc, float* sm)
{
    float* As = sm;                 // 3 * 5120
    float* Bs = sm + 3 * 5120;      // 3 * 2176

    const int tid = threadIdx.x;
    const int bm = blockIdx.y * 256;
    const int bn = blockIdx.x * 128;
    const int warp = tid >> 5;
    const int warpm = warp & 3, warpn = warp >> 2;
    const int lane = tid & 31;
    const int lr = lane >> 2, lc = lane & 3;
    const int nT = K >> 4;

    // A staging: 256x16 = 4096 elems, 4 cp16/thread
    const int ar = tid >> 2;                 // 0..63
    const int aj = (tid & 3) << 2;
    const long aoff0 = (long)(bm + ar) * lda + aj;
    const long aoff1 = (long)(bm + ar + 64) * lda + aj;
    const long aoff2 = (long)(bm + ar + 128) * lda + aj;
    const long aoff3 = (long)(bm + ar + 192) * lda + aj;
    // B staging: 16x128 = 2048 elems, 2 cp16/thread
    const long boffg = (long)(tid >> 4) * ldb + bn + ((tid & 15) << 3);

    const unsigned asb = (unsigned)__cvta_generic_to_shared(As);
    const unsigned bsb = (unsigned)__cvta_generic_to_shared(Bs);
    const unsigned sa0 = asb + (unsigned)(ar * 20 + aj) * 4u;
    const unsigned sa1 = sa0 + 64u * 20u * 4u;
    const unsigned sa2 = sa0 + 128u * 20u * 4u;
    const unsigned sa3 = sa0 + 192u * 20u * 4u;
    const unsigned sb0 = bsb + (unsigned)((tid >> 4) * 136 + ((tid & 15) << 3)) * 4u;

    auto load_tile = [&](int t, int st) {
        int k0 = t << 4;
        const float* Ab = A; const float* Bb = B; int kk = k0;
        if (SPLIT && k0 >= Ksplit) { Ab = A2; Bb = B2; kk = k0 - Ksplit; }
        unsigned oa = (unsigned)st * (5120 * 4u);
        unsigned ob = (unsigned)st * (2176 * 4u);
        cp16(sa0 + oa, Ab + aoff0 + kk);
        cp16(sa1 + oa, Ab + aoff1 + kk);
        cp16(sa2 + oa, Ab + aoff2 + kk);
        cp16(sa3 + oa, Ab + aoff3 + kk);
        const float* bp = Bb + (long)kk * ldb + boffg;
        cp16(sb0 + ob, bp);
        cp16(sb0 + ob + 16u, bp + 4);
    };

#pragma unroll
    for (int st = 0; st < 2; st++) {
        if (st < nT) load_tile(st, st);
        asm volatile("cp.async.commit_group;");
    }

    float acc[4][8][4] = {};
    const int afb = (warpm * 64 + lr) * 20 + lc;
    const int bfb = lc * 136 + warpn * 64 + lr;

    for (int t = 0; t < nT; t++) {
        asm volatile("cp.async.wait_group 1;");
        __syncthreads();
        if (t + 2 < nT) load_tile(t + 2, (t + 2) % 3);
        asm volatile("cp.async.commit_group;");

        const float* as = As + (t % 3) * 5120;
        const float* bs = Bs + (t % 3) * 2176;
#pragma unroll
        for (int ks = 0; ks < 2; ks++) {
            unsigned af[4][4];
#pragma unroll
            for (int mi = 0; mi < 4; mi++) {
                int base = afb + mi * 320 + ks * 8;
                af[mi][0] = __float_as_uint(as[base]);
                af[mi][1] = __float_as_uint(as[base + 160]);
                af[mi][2] = __float_as_uint(as[base + 4]);
                af[mi][3] = __float_as_uint(as[base + 164]);
            }
            unsigned bf[8][2];
#pragma unroll
            for (int ni = 0; ni < 8; ni++) {
                int base = bfb + ni * 8 + ks * 1088;
                bf[ni][0] = __float_as_uint(bs[base]);
                bf[ni][1] = __float_as_uint(bs[base + 544]);
            }
#pragma unroll
            for (int mi = 0; mi < 4; mi++)
#pragma unroll
                for (int ni = 0; ni < 8; ni++)
                    MMA_TF32(acc[mi][ni], af[mi], bf[ni]);
        }
    }

#pragma unroll
    for (int mi = 0; mi < 4; mi++)
#pragma unroll
        for (int ni = 0; ni < 8; ni++) {
            int row0 = bm + warpm * 64 + mi * 16 + lr;
            int col = bn + warpn * 64 + ni * 8 + lc * 2;
#pragma unroll
            for (int rr = 0; rr < 2; rr++) {
                int row = row0 + rr * 8;
                *(float2*)&C[(long)row * ldc + col] =
                    make_float2(acc[mi][ni][rr * 2], acc[mi][ni][rr * 2 + 1]);
            }
        }
}

// plain batched wrapper (W precompute)
__global__ void __launch_bounds__(256) tc_plain(
    const float* __restrict__ A, const float* __restrict__ B,
    float* __restrict__ C, int K, int lda, int ldb, int ldc,
    long sA, long sB, long sC)
{
    extern __shared__ float dynsm[];
    int z = blockIdx.z;
    gemm_body<false>(A + z * sA, nullptr, B + z * sB, nullptr, 0,
                     C + z * sC, K, lda, ldb, ldc, dynsm);
}

// batched unify: z=0 l(K=768), z=1 v(K=640), z=2 padded-a(K=208)
__global__ void __launch_bounds__(256) unify_b(
    const float* __restrict__ l, const float* __restrict__ v,
    const float* __restrict__ pa,
    const float* __restrict__ wl, const float* __restrict__ wv,
    const float* __restrict__ pwa, float* __restrict__ tmpb)
{
    extern __shared__ float dynsm[];
    int z = blockIdx.z;
    const float* A; const float* B; int K;
    if (z == 0)      { A = l;  B = wl;  K = 768; }
    else if (z == 1) { A = v;  B = wv;  K = 640; }
    else             { A = pa; B = pwa; K = KA_PAD; }
    gemm_body<false>(A, nullptr, B, nullptr, 0,
                     tmpb + (long)z * USZ, K, K, DIM, DIM, dynsm);
}

// batched minus GEMM: tmp[s] = qin[s] @ minus_top[i] + ctx[s] @ W[i], i=s*2+L
template<int LAYER>
__global__ void __launch_bounds__(256) minus_b(
    const float* __restrict__ Ub, const float* __restrict__ Qprev,
    const float* __restrict__ ctxb, const float* __restrict__ minus_w,
    const float* __restrict__ Wb, float* __restrict__ tmpb)
{
    extern __shared__ float dynsm[];
    int s = blockIdx.z;
    const float* A = (LAYER == 0) ? Ub + (s / 3) * USZ : Qprev + s * USZ;
    int i = s * 2 + LAYER;
    gemm_body<true>(A, ctxb + s * USZ,
                    minus_w + (long)i * 2 * DIM * DIM,
                    Wb + (long)i * DIM * DIM,
                    DIM, tmpb + s * USZ, 2 * DIM, DIM, DIM, DIM, dynsm);
}

// pad a [4096,205]->[4096,208] and wa [205,512]->[208,512] (zero fill)
__global__ void pad_a_kernel(
    const float* __restrict__ a, const float* __restrict__ wa,
    float* __restrict__ pa, float* __restrict__ pwa)
{
    int idx = blockIdx.x * 256 + threadIdx.x;
    const int NA = 4096 * KA_PAD;            // 851968
    const int NB = KA_PAD * DIM;             // 106496
    if (idx < NA) {
        int r = idx / KA_PAD, c = idx - r * KA_PAD;
        pa[idx] = (c < 205) ? a[r * 205 + c] : 0.f;
    } else if (idx < NA + NB) {
        int j = idx - NA;
        int r = j >> 9, c = j & 511;
        pwa[j] = (r < 205) ? wa[r * DIM + c] : 0.f;
    }
}

// ---------------------------------------------------------------------------
// Persistent-K fused attention (verified round-9): one CTA per z (grid 576).
// ---------------------------------------------------------------------------
#define L2E 1.44269504f

template<int LAYER>
__global__ void __launch_bounds__(256, 1) attn_fused(
    const float* __restrict__ Ub, const float* __restrict__ Qprev,
    float* __restrict__ ctxb,
    const float* __restrict__ m0, const float* __restrict__ m1,
    const float* __restrict__ m2, const float* __restrict__ cvec)
{
    extern __shared__ float sm[];
    float* Ks   = sm;                  // 512*68
    float* Qs   = Ks + 512 * 68;       // 32*68
    float* Ps   = Qs + 32 * 68;        // 32*516 (also ctx partial buffer 8*2048)
    float* red  = Ps + 32 * 516;       // 8*32
    float* rmax = red + 256;           // 32
    float* rinv = rmax + 32;           // 32

    const int z = blockIdx.x;
    const int s = z >> 6;
    const int bb = (z >> 3) & 7;
    const int hh = z & 7;

    const int tid = threadIdx.x;
    const int w = tid >> 5;
    const int lane = tid & 31;
    const int lr = lane >> 2, lc = lane & 3;

    const int kv = kvi_of(s);
    const float* q0p = Ub + (s / 3) * USZ;
    const float* qin = (LAYER == 0) ? q0p : Qprev + s * USZ;
    const float* kvp = Ub + kv * USZ;
    const float* maskp = ((kv == 0) ? m0 : (kv == 1) ? m1 : m2) + bb * SEQ;

    const float* Qg  = qin + (long)bb * SEQ * DIM + hh * HD;
    const float* Q0g = q0p + (long)bb * SEQ * DIM + hh * HD;
    const float* Kg  = kvp + (long)bb * SEQ * DIM + hh * HD;

    const float SCL = 0.125f * L2E;    // scores scale in log2 domain
    float cv = 0.f, pscale = 1e8f * L2E;
    if (LAYER == 1) { cv = cvec[s * 2 + 1]; pscale = (1.f + cv) * 1e8f * L2E; }

    // ---- stage K (512x64), resident for whole CTA ----
    {
        unsigned ksb = (unsigned)__cvta_generic_to_shared(Ks);
        int r = tid >> 4, c = (tid & 15) << 2;
#pragma unroll
        for (int i = 0; i < 32; i++) {
            int rr = r + i * 16;
            cp16(ksb + (unsigned)(rr * 68 + c) * 4u, Kg + (long)rr * DIM + c);
        }
        asm volatile("cp.async.commit_group;");
        asm volatile("cp.async.wait_group 0;");
    }
    __syncthreads();

    // mask penalties for this warp's score columns (reused across q-tiles)
    const int nbase = w * 64;
    float mpen[8][2];
#pragma unroll
    for (int ni = 0; ni < 8; ni++) {
        mpen[ni][0] = pscale * (1.f - maskp[nbase + ni * 8 + lc * 2]);
        mpen[ni][1] = pscale * (1.f - maskp[nbase + ni * 8 + lc * 2 + 1]);
    }

    for (int qt = 0; qt < 16; qt++) {
        const int row0 = qt * 32;

        // ---- stage Q tile (32x64); layer 1 stages Qeff = Q1 + c*Q0 ----
        if (LAYER == 0) {
            unsigned qsb = (unsigned)__cvta_generic_to_shared(Qs);
#pragma unroll
            for (int i = 0; i < 2; i++) {
                int idx = tid + i * 256;
                int qr = idx >> 4, qc = (idx & 15) << 2;
                cp16(qsb + (unsigned)(qr * 68 + qc) * 4u,
                     Qg + (long)(row0 + qr) * DIM + qc);
            }
            asm volatile("cp.async.commit_group;");
            asm volatile("cp.async.wait_group 0;");
        } else {
#pragma unroll
            for (int i = 0; i < 8; i++) {
                int idx = tid + i * 256;
                int qr = idx >> 6, qc = idx & 63;
                long go = (long)(row0 + qr) * DIM + qc;
                Qs[qr * 68 + qc] = Qg[go] + cv * Q0g[go];
            }
        }
        __syncthreads();   // Qs ready; fences prev iteration's Ps/rinv reads

        // ---- scores: warp w owns seq cols [w*64, w*64+64) ----
        float acc[2][8][4] = {};
#pragma unroll
        for (int ks = 0; ks < 8; ks++) {
            unsigned af[2][4];
#pragma unroll
            for (int mi = 0; mi < 2; mi++) {
                const float* q = &Qs[(mi * 16 + lr) * 68 + ks * 8 + lc];
                af[mi][0] = __float_as_uint(q[0]);
                af[mi][1] = __float_as_uint(q[8 * 68]);
                af[mi][2] = __float_as_uint(q[4]);
                af[mi][3] = __float_as_uint(q[8 * 68 + 4]);
            }
#pragma unroll
            for (int ni = 0; ni < 8; ni++) {
                unsigned bf[2];
                const float* kp = &Ks[(nbase + ni * 8 + lr) * 68 + ks * 8 + lc];
                bf[0] = __float_as_uint(kp[0]);
                bf[1] = __float_as_uint(kp[4]);
#pragma unroll
                for (int mi = 0; mi < 2; mi++)
                    MMA_TF32(acc[mi][ni], af[mi], bf);
            }
        }

        // ---- scale (log2 domain) + mask ----
#pragma unroll
        for (int mi = 0; mi < 2; mi++)
#pragma unroll
            for (int ni = 0; ni < 8; ni++) {
                acc[mi][ni][0] = acc[mi][ni][0] * SCL - mpen[ni][0];
                acc[mi][ni][1] = acc[mi][ni][1] * SCL - mpen[ni][1];
                acc[mi][ni][2] = acc[mi][ni][2] * SCL - mpen[ni][0];
                acc[mi][ni][3] = acc[mi][ni][3] * SCL - mpen[ni][1];
            }

        // ---- softmax: row max ----
        float lred[4];
#pragma unroll
        for (int i = 0; i < 4; i++) {
            int mi = i >> 1, rr = i & 1;
            float m = -INFINITY;
#pragma unroll
            for (int ni = 0; ni < 8; ni++)
                m = fmaxf(m, fmaxf(acc[mi][ni][rr * 2], acc[mi][ni][rr * 2 + 1]));
            m = fmaxf(m, __shfl_xor_sync(0xffffffffu, m, 1));
            m = fmaxf(m, __shfl_xor_sync(0xffffffffu, m, 2));
            lred[i] = m;
        }
        if (lc == 0)
#pragma unroll
            for (int i = 0; i < 4; i++)
                red[w * 32 + (i >> 1) * 16 + (i & 1) * 8 + lr] = lred[i];
        __syncthreads();
        if (tid < 32) {
            float m = red[tid];
#pragma unroll
            for (int ww = 1; ww < 8; ww++) m = fmaxf(m, red[ww * 32 + tid]);
            rmax[tid] = m;
        }
        __syncthreads();

        // ---- exp2 -> Ps (unnormalized), row sum ----
#pragma unroll
        for (int i = 0; i < 4; i++) {
            int mi = i >> 1, rr = i & 1;
            int row = mi * 16 + rr * 8 + lr;
            float rm = rmax[row];
            float* prow = &Ps[row * 516 + nbase + lc * 2];
            float sum = 0.f;
#pragma unroll
            for (int ni = 0; ni < 8; ni++) {
                float e0 = exp2f(acc[mi][ni][rr * 2] - rm);
                float e1 = exp2f(acc[mi][ni][rr * 2 + 1] - rm);
                prow[ni * 8] = e0; prow[ni * 8 + 1] = e1;
                sum += e0 + e1;
            }
            sum += __shfl_xor_sync(0xffffffffu, sum, 1);
            sum += __shfl_xor_sync(0xffffffffu, sum, 2);
            lred[i] = sum;
        }
        if (lc == 0)
#pragma unroll
            for (int i = 0; i < 4; i++)
                red[w * 32 + (i >> 1) * 16 + (i & 1) * 8 + lr] = lred[i];
        __syncthreads();
        if (tid < 32) {
            float sum = 0.f;
#pragma unroll
            for (int ww = 0; ww < 8; ww++) sum += red[ww * 32 + tid];
            rinv[tid] = 1.f / sum;
        }
        __syncthreads();

        // ---- ctx partials: warp w takes k-slice [w*64,w*64+64), all 64 cols
        float cacc[2][8][4] = {};
#pragma unroll
        for (int ks = 0; ks < 8; ks++) {
            const int kg = w * 64 + ks * 8;
            unsigned af[2][4];
#pragma unroll
            for (int mi = 0; mi < 2; mi++) {
                const float* p = &Ps[(mi * 16 + lr) * 516 + kg + lc];
                af[mi][0] = __float_as_uint(p[0]);
                af[mi][1] = __float_as_uint(p[8 * 516]);
                af[mi][2] = __float_as_uint(p[4]);
                af[mi][3] = __float_as_uint(p[8 * 516 + 4]);
            }
#pragma unroll
            for (int ni = 0; ni < 8; ni++) {
                unsigned bf[2];
                const float* kp = &Ks[(kg + lc) * 68 + ni * 8 + lr];
                bf[0] = __float_as_uint(kp[0]);
                bf[1] = __float_as_uint(kp[4 * 68]);
#pragma unroll
                for (int mi = 0; mi < 2; mi++)
                    MMA_TF32(cacc[mi][ni], af[mi], bf);
            }
        }
        __syncthreads();   // all Ps reads complete before overlay

        // store partials into Ps region, per-row rotated units (no conflicts)
        {
            float* pb = Ps + w * 2048;
#pragma unroll
            for (int mi = 0; mi < 2; mi++)
#pragma unroll
                for (int rr = 0; rr < 2; rr++) {
                    int row = mi * 16 + rr * 8 + lr;
#pragma unroll
                    for (int ni = 0; ni < 8; ni++) {
                        int u = (ni * 4 + lc + row * 4) & 31;
                        *(float2*)&pb[row * 64 + u * 2] =
                            make_float2(cacc[mi][ni][rr * 2],
                                        cacc[mi][ni][rr * 2 + 1]);
                    }
                }
        }
        __syncthreads();

        // reduce 8 partials, scale by rinv, store ctx (coalesced float2)
        float* ctxg = ctxb + (long)s * USZ + (long)bb * SEQ * DIM
                    + (long)row0 * DIM + hh * HD;
#pragma unroll
        for (int i = 0; i < 4; i++) {
            int idx = tid + i * 256;       // float2 unit over 32x32 units
            int row = idx >> 5;
            int u = idx & 31;
            int up = (u + row * 4) & 31;
            float sx = 0.f, sy = 0.f;
#pragma unroll
            for (int ww = 0; ww < 8; ww++) {
                float2 vv = *(float2*)&Ps[ww * 2048 + row * 64 + up * 2];
                sx += vv.x; sy += vv.y;
            }
            float inv = rinv[row];
            *(float2*)&ctxg[(long)row * DIM + u * 2] =
                make_float2(sx * inv, sy * inv);
        }
        // next iteration's first __syncthreads orders Ps reuse
    }
}

// ---------------------------------------------------------------------------
// LayerNorm: warp-per-row, float4 loads, shuffle-only reductions (no BAR).
// 8 rows per CTA. param offset = (row >> 12) * pstride.
// ---------------------------------------------------------------------------
__global__ void __launch_bounds__(256) ln_all(
    const float* __restrict__ X, float* __restrict__ Y,
    const float* __restrict__ g, const float* __restrict__ b, int pstride)
{
    const long row = (long)blockIdx.x * 8 + (threadIdx.x >> 5);
    const int lane = threadIdx.x & 31;
    const int pi = (int)(row >> 12);
    const float* gp = g + (long)pi * pstride;
    const float* bp = b + (long)pi * pstride;
    const float4* x = (const float4*)(X + row * DIM) + lane;
    float4* y = (float4*)(Y + row * DIM) + lane;

    float4 v[4];
#pragma unroll
    for (int i = 0; i < 4; i++) v[i] = x[i * 32];

    float sum = 0.f;
#pragma unroll
    for (int i = 0; i < 4; i++)
        sum += v[i].x + v[i].y + v[i].z + v[i].w;
#pragma unroll
    for (int o = 16; o > 0; o >>= 1)
        sum += __shfl_xor_sync(0xffffffffu, sum, o);
    float mu = sum * (1.f / DIM);

    float q = 0.f;
#pragma unroll
    for (int i = 0; i < 4; i++) {
        v[i].x -= mu; v[i].y -= mu; v[i].z -= mu; v[i].w -= mu;
        q += v[i].x * v[i].x + v[i].y * v[i].y
           + v[i].z * v[i].z + v[i].w * v[i].w;
    }
#pragma unroll
    for (int o = 16; o > 0; o >>= 1)
        q += __shfl_xor_sync(0xffffffffu, q, o);
    float rstd = rsqrtf(q * (1.f / DIM) + 1e-5f);

    const float4* g4 = (const float4*)gp + lane;
    const float4* b4 = (const float4*)bp + lane;
#pragma unroll
    for (int i = 0; i < 4; i++) {
        float4 gg = g4[i * 32], bb = b4[i * 32];
        float4 o;
        o.x = v[i].x * rstd * gg.x + bb.x;
        o.y = v[i].y * rstd * gg.y + bb.y;
        o.z = v[i].z * rstd * gg.z + bb.z;
        o.w = v[i].w * rstd * gg.w + bb.w;
        y[i * 32] = o;
    }
}

// ---------------------------------------------------------------------------
// Pooling
// ---------------------------------------------------------------------------
__global__ void pool_init(float* s, float* m, int n)
{
    int i = blockIdx.x * blockDim.x + threadIdx.x;
    if (i < n) { s[i] = 0.f; m[i] = -INFINITY; }
}

__device__ __forceinline__ void atomicMaxF(float* addr, float val)
{
    int old = __float_as_int(*addr);
    while (__int_as_float(old) < val) {
        int assumed = old;
        old = atomicCAS((int*)addr, assumed, __float_as_int(val));
        if (old == assumed) break;
    }
}

// grid (16, 3 slots, 4 row-chunks); slot g <- streams {g, g+3, g+6}
__global__ void __launch_bounds__(256) pool_b(
    const float* __restrict__ Qb, float* __restrict__ sum,
    float* __restrict__ mx, int layer)
{
    int idx = blockIdx.x * 256 + threadIdx.x;   // (b,d)
    int bb = idx >> 9, d = idx & 511;
    int g = blockIdx.y;
    int r0 = blockIdx.z * 128;
    float s = 0.f, m = -INFINITY;
#pragma unroll
    for (int t = 0; t < 3; t++) {
        const float* p = Qb + (long)(g + t * 3) * USZ
                       + (long)bb * SEQ * DIM + (long)r0 * DIM + d;
        for (int r = 0; r < 128; r++) {
            float v = p[(long)r * DIM];
            s += v;
            m = fmaxf(m, v);
        }
    }
    int k = g * 2 + layer;
    atomicAdd(&sum[k * 4096 + idx], s);
    atomicMaxF(&mx[k * 4096 + idx], m);
}

// ---------------------------------------------------------------------------
// Classifier
// ---------------------------------------------------------------------------
__global__ void __launch_bounds__(256) clf_kernel(
    const float* __restrict__ sum, const float* __restrict__ mx,
    const float* __restrict__ W, float* __restrict__ out)
{
    int bb = blockIdx.x / 9, cls = blockIdx.x % 9;
    int tid = threadIdx.x;
    float acc = 0.f;
    for (int j = tid; j < 3072; j += 256) {
        int k = j >> 9, d = j & 511;
        float sm = sum[k * 4096 + bb * 512 + d] * (1.f / 1536.f);
        float mv = mx[k * 4096 + bb * 512 + d];
        acc += sm * W[(long)j * 9 + cls] + mv * W[(long)(3072 + j) * 9 + cls];
    }
    __shared__ float red[256];
    red[tid] = acc;
    __syncthreads();
    for (int s = 128; s > 0; s >>= 1) {
        if (tid < s) red[tid] += red[tid + s];
        __syncthreads();
    }
    if (tid == 0) out[bb * 9 + cls] = red[0];
}

// ---------------------------------------------------------------------------
// Host orchestration (single stream; no stream/event creation allowed)
// ---------------------------------------------------------------------------
extern "C" void kernel_launch(void* const* d_in, const int* in_sizes, int n_in,
                              void* d_out, int out_size)
{
    const float* l      = (const float*)d_in[0];
    const float* v      = (const float*)d_in[1];
    const float* a      = (const float*)d_in[2];
    const float* l_mask = (const float*)d_in[3];
    const float* v_mask = (const float*)d_in[4];
    const float* a_mask = (const float*)d_in[5];
    const float* wl     = (const float*)d_in[6];
    const float* wv     = (const float*)d_in[7];
    const float* wa     = (const float*)d_in[8];
    const float* n1_g   = (const float*)d_in[9];
    const float* n1_b   = (const float*)d_in[10];
    const float* proj_w = (const float*)d_in[11];
    const float* minus_w= (const float*)d_in[12];
    const float* n2_g   = (const float*)d_in[13];
    const float* n2_b   = (const float*)d_in[14];
    const float* cvec   = (const float*)d_in[15];
    const float* clf_w  = (const float*)d_in[16];
    float* out          = (float*)d_out;

    float *pU, *pqA, *pqB, *pctx, *ptmp, *pW, *psum, *pmax;
    cudaGetSymbolAddress((void**)&pU, g_U);
    cudaGetSymbolAddress((void**)&pqA, g_qA);
    cudaGetSymbolAddress((void**)&pqB, g_qB);
    cudaGetSymbolAddress((void**)&pctx, g_ctx);
    cudaGetSymbolAddress((void**)&ptmp, g_tmp);
    cudaGetSymbolAddress((void**)&pW, g_W);
    cudaGetSymbolAddress((void**)&psum, g_sum);
    cudaGetSymbolAddress((void**)&pmax, g_max);

    // prologue pad scratch lives in g_ctx (free until attention)
    float* pad_a = pctx;
    float* pad_wa = pctx + 4096 * KA_PAD;

    const int SMEM_ATTN = (512 * 68 + 32 * 68 + 32 * 516 + 256 + 64) * 4;
    cudaFuncSetAttribute(attn_fused<0>,
        cudaFuncAttributeMaxDynamicSharedMemorySize, SMEM_ATTN);
    cudaFuncSetAttribute(attn_fused<1>,
        cudaFuncAttributeMaxDynamicSharedMemorySize, SMEM_ATTN);
    cudaFuncSetAttribute(tc_plain,
        cudaFuncAttributeMaxDynamicSharedMemorySize, GEMM_SMEM);
    cudaFuncSetAttribute(unify_b,
        cudaFuncAttributeMaxDynamicSharedMemorySize, GEMM_SMEM);
    cudaFuncSetAttribute(minus_b<0>,
        cudaFuncAttributeMaxDynamicSharedMemorySize, GEMM_SMEM);
    cudaFuncSetAttribute(minus_b<1>,
        cudaFuncAttributeMaxDynamicSharedMemorySize, GEMM_SMEM);

    pool_init<<<96, 256>>>(psum, pmax, 6 * BATCH * DIM);

    // pad a + wa into scratch
    pad_a_kernel<<<3744, 256>>>(a, wa, pad_a, pad_wa);

    // W[i] = proj_w[i] @ minus_w[i][512:1024]  (batched over 18 blocks)
    tc_plain<<<dim3(4, 2, 18), 256, GEMM_SMEM>>>(
        proj_w, minus_w + (long)DIM * DIM, pW, DIM, DIM, DIM, DIM,
        (long)DIM * DIM, (long)2 * DIM * DIM, (long)DIM * DIM);

    // --- Unify (all 3 modalities in one launch) + one merged LN ---
    unify_b<<<dim3(4, 16, 3), 256, GEMM_SMEM>>>(l, v, pad_a, wl, wv, pad_wa, ptmp);
    ln_all<<<3 * 512, 256>>>(ptmp, pU, n1_g, n1_b, 0);

    // --- layer 0 (all 9 streams batched) ---
    attn_fused<0><<<576, 256, SMEM_ATTN>>>(
        pU, nullptr, pctx, l_mask, v_mask, a_mask, cvec);
    minus_b<0><<<dim3(4, 16, 9), 256, GEMM_SMEM>>>(
        pU, nullptr, pctx, minus_w, pW, ptmp);
    ln_all<<<9 * 512, 256>>>(ptmp, pqA, n2_g, n2_b, 2 * DIM);
    pool_b<<<dim3(16, 3, 4), 256>>>(pqA, psum, pmax, 0);

    // --- layer 1 ---
    attn_fused<1><<<576, 256, SMEM_ATTN>>>(
        pU, pqA, pctx, l_mask, v_mask, a_mask, cvec);
    minus_b<1><<<dim3(4, 16, 9), 256, GEMM_SMEM>>>(
        pU, pqA, pctx, minus_w, pW, ptmp);
    ln_all<<<9 * 512, 256>>>(ptmp, pqB, n2_g + DIM, n2_b + DIM, 2 * DIM);
    pool_b<<<dim3(16, 3, 4), 256>>>(pqB, psum, pmax, 1);

    clf_kernel<<<BATCH * 9, 256>>>(psum, pmax, clf_w, out);
}

// round 13
// speedup vs baseline: 1.1150x; 1.0509x over previous
#include <cuda_runtime.h>
#include <math.h>

// ---------------------------------------------------------------------------
// Problem constants
// ---------------------------------------------------------------------------
#define BATCH 8
#define NH 8
#define SEQ 512
#define DIM 512
#define HD 64
#define USZ ((long)BATCH * SEQ * DIM)       // 2097152 floats per stream buffer
#define KA_PAD 224                          // a-modality K padded to 32

// gemm dynamic smem: As 3*256*36 + Bs 3*32*136 floats = 162816 bytes
#define GEMM_SMEM ((3 * 9216 + 3 * 4352) * 4)

// ---------------------------------------------------------------------------
// Scratch (device globals; no allocations allowed)
// ---------------------------------------------------------------------------
__device__ float g_U[3 * 2097152];          // unified l,v,a
__device__ float g_qA[9 * 2097152];         // layer-0 outputs per stream
__device__ float g_qB[9 * 2097152];         // layer-1 outputs per stream
__device__ float g_ctx[9 * 2097152];        // ctx; also prologue pad scratch
__device__ float g_tmp[9 * 2097152];
__device__ float g_W[18 * DIM * DIM];       // proj @ minus_bottom
__device__ float g_sum[6 * BATCH * DIM];
__device__ float g_max[6 * BATCH * DIM];

// ---------------------------------------------------------------------------
// MMA / cp.async helpers
// ---------------------------------------------------------------------------
#define MMA_TF32(d, a, b)                                                     \
    asm volatile(                                                             \
        "mma.sync.aligned.m16n8k8.row.col.f32.tf32.tf32.f32 "                 \
        "{%0,%1,%2,%3},{%4,%5,%6,%7},{%8,%9},{%0,%1,%2,%3};"                  \
        : "+f"(d[0]), "+f"(d[1]), "+f"(d[2]), "+f"(d[3])                      \
        : "r"(a[0]), "r"(a[1]), "r"(a[2]), "r"(a[3]), "r"(b[0]), "r"(b[1]))

__device__ __forceinline__ void cp16(unsigned dst, const float* src)
{
    asm volatile("cp.async.cg.shared.global [%0], [%1], 16;"
                 :: "r"(dst), "l"(src));
}

// stream tables: qsrc[s] = s/3 ; kvi[s] via 2-bit packed code {0,1,2,1,0,2,2,0,1}
__device__ __forceinline__ int kvi_of(int s) { return (75876 >> (2 * s)) & 3; }

// ---------------------------------------------------------------------------
// Shared GEMM body: NN, CTA tile 256x128x32, cp.async 3-stage.
// 8 warps: warpm = warp&3 (64-row slabs), warpn = warp>>2 (64-col slabs).
// BK=32 halves mainloop barrier/wait events vs BK=16.
// K%32==0, lda%4==0, ldb%4==0, 16B-aligned ptrs, M%256==0, N%128==0.
// SPLIT: k >= Ksplit reads A2/B2 (k rebased; Ksplit%32==0).
// Dynamic smem: As[3][9216] (256 rows padded to 36), Bs[3][4352] ([32][136]).
// ---------------------------------------------------------------------------
template<bool SPLIT>
__device__ __forceinline__ void gemm_body(
    const float* __restrict__ A, const float* __restrict__ A2,
    const float* __restrict__ B, const float* __restrict__ B2,
    int Ksplit, float* __restrict__ C,
    int K, int lda, int ldb, int ldc, float* sm)
{
    float* As = sm;                 // 3 * 9216
    float* Bs = sm + 3 * 9216;      // 3 * 4352

    const int tid = threadIdx.x;
    const int bm = blockIdx.y * 256;
    const int bn = blockIdx.x * 128;
    const int warp = tid >> 5;
    const int warpm = warp & 3, warpn = warp >> 2;
    const int lane = tid & 31;
    const int lr = lane >> 2, lc = lane & 3;
    const int nT = K >> 5;

    // A staging: 256x32 = 8192 elems, 8 cp16/thread
    const int ar = tid >> 2;                 // 0..63
    const int aj = (tid & 3) << 2;           // 0,4,8,12 (+16 second group)
    const long aoff0 = (long)(bm + ar) * lda + aj;
    const long aoff1 = (long)(bm + ar + 64) * lda + aj;
    const long aoff2 = (long)(bm + ar + 128) * lda + aj;
    const long aoff3 = (long)(bm + ar + 192) * lda + aj;
    // B staging: 32x128 = 4096 elems, 4 cp16/thread
    const int brow = tid >> 4;               // 0..15 (+16 second half)
    const long boffg = (long)brow * ldb + bn + ((tid & 15) << 3);

    const unsigned asb = (unsigned)__cvta_generic_to_shared(As);
    const unsigned bsb = (unsigned)__cvta_generic_to_shared(Bs);
    const unsigned sa0 = asb + (unsigned)(ar * 36 + aj) * 4u;
    const unsigned sa1 = sa0 + 64u * 36u * 4u;
    const unsigned sa2 = sa0 + 128u * 36u * 4u;
    const unsigned sa3 = sa0 + 192u * 36u * 4u;
    const unsigned sb0 = bsb + (unsigned)(brow * 136 + ((tid & 15) << 3)) * 4u;

    auto load_tile = [&](int t, int st) {
        int k0 = t << 5;
        const float* Ab = A; const float* Bb = B; int kk = k0;
        if (SPLIT && k0 >= Ksplit) { Ab = A2; Bb = B2; kk = k0 - Ksplit; }
        unsigned oa = (unsigned)st * (9216 * 4u);
        unsigned ob = (unsigned)st * (4352 * 4u);
        cp16(sa0 + oa, Ab + aoff0 + kk);
        cp16(sa0 + oa + 64u, Ab + aoff0 + kk + 16);
        cp16(sa1 + oa, Ab + aoff1 + kk);
        cp16(sa1 + oa + 64u, Ab + aoff1 + kk + 16);
        cp16(sa2 + oa, Ab + aoff2 + kk);
        cp16(sa2 + oa + 64u, Ab + aoff2 + kk + 16);
        cp16(sa3 + oa, Ab + aoff3 + kk);
        cp16(sa3 + oa + 64u, Ab + aoff3 + kk + 16);
        const float* bp = Bb + (long)kk * ldb + boffg;
        cp16(sb0 + ob, bp);
        cp16(sb0 + ob + 16u, bp + 4);
        const float* bp2 = bp + 16 * ldb;
        cp16(sb0 + ob + 16u * 136u * 4u, bp2);
        cp16(sb0 + ob + 16u * 136u * 4u + 16u, bp2 + 4);
    };

#pragma unroll
    for (int st = 0; st < 2; st++) {
        if (st < nT) load_tile(st, st);
        asm volatile("cp.async.commit_group;");
    }

    float acc[4][8][4] = {};
    const int afb = (warpm * 64 + lr) * 36 + lc;
    const int bfb = lc * 136 + warpn * 64 + lr;

    for (int t = 0; t < nT; t++) {
        asm volatile("cp.async.wait_group 1;");
        __syncthreads();
        if (t + 2 < nT) load_tile(t + 2, (t + 2) % 3);
        asm volatile("cp.async.commit_group;");

        const float* as = As + (t % 3) * 9216;
        const float* bs = Bs + (t % 3) * 4352;
#pragma unroll
        for (int ks = 0; ks < 4; ks++) {
            unsigned af[4][4];
#pragma unroll
            for (int mi = 0; mi < 4; mi++) {
                int base = afb + mi * 576 + ks * 8;
                af[mi][0] = __float_as_uint(as[base]);
                af[mi][1] = __float_as_uint(as[base + 288]);
                af[mi][2] = __float_as_uint(as[base + 4]);
                af[mi][3] = __float_as_uint(as[base + 292]);
            }
            unsigned bf[8][2];
#pragma unroll
            for (int ni = 0; ni < 8; ni++) {
                int base = bfb + ni * 8 + ks * 1088;
                bf[ni][0] = __float_as_uint(bs[base]);
                bf[ni][1] = __float_as_uint(bs[base + 544]);
            }
#pragma unroll
            for (int mi = 0; mi < 4; mi++)
#pragma unroll
                for (int ni = 0; ni < 8; ni++)
                    MMA_TF32(acc[mi][ni], af[mi], bf[ni]);
        }
    }

#pragma unroll
    for (int mi = 0; mi < 4; mi++)
#pragma unroll
        for (int ni = 0; ni < 8; ni++) {
            int row0 = bm + warpm * 64 + mi * 16 + lr;
            int col = bn + warpn * 64 + ni * 8 + lc * 2;
#pragma unroll
            for (int rr = 0; rr < 2; rr++) {
                int row = row0 + rr * 8;
                *(float2*)&C[(long)row * ldc + col] =
                    make_float2(acc[mi][ni][rr * 2], acc[mi][ni][rr * 2 + 1]);
            }
        }
}

// combined prologue: z 0..2 = unify (l K=768, v K=640, padded-a K=224),
// z 3..20 = W[i] = proj_w[i] @ minus_w[i][512:1024] (i = z-3, y<2 only)
__global__ void __launch_bounds__(256) prol_b(
    const float* __restrict__ l, const float* __restrict__ v,
    const float* __restrict__ pa,
    const float* __restrict__ wl, const float* __restrict__ wv,
    const float* __restrict__ pwa, float* __restrict__ tmpb,
    const float* __restrict__ proj_w, const float* __restrict__ minus_w,
    float* __restrict__ Wb)
{
    extern __shared__ float dynsm[];
    int z = blockIdx.z;
    if (z < 3) {
        const float* A; const float* B; int K;
        if (z == 0)      { A = l;  B = wl;  K = 768; }
        else if (z == 1) { A = v;  B = wv;  K = 640; }
        else             { A = pa; B = pwa; K = KA_PAD; }
        gemm_body<false>(A, nullptr, B, nullptr, 0,
                         tmpb + (long)z * USZ, K, K, DIM, DIM, dynsm);
    } else {
        if (blockIdx.y >= 2) return;
        int i = z - 3;
        gemm_body<false>(proj_w + (long)i * DIM * DIM, nullptr,
                         minus_w + (long)i * 2 * DIM * DIM + (long)DIM * DIM,
                         nullptr, 0,
                         Wb + (long)i * DIM * DIM, DIM, DIM, DIM, DIM, dynsm);
    }
}

// batched minus GEMM: tmp[s] = qin[s] @ minus_top[i] + ctx[s] @ W[i], i=s*2+L
template<int LAYER>
__global__ void __launch_bounds__(256) minus_b(
    const float* __restrict__ Ub, const float* __restrict__ Qprev,
    const float* __restrict__ ctxb, const float* __restrict__ minus_w,
    const float* __restrict__ Wb, float* __restrict__ tmpb)
{
    extern __shared__ float dynsm[];
    int s = blockIdx.z;
    const float* A = (LAYER == 0) ? Ub + (s / 3) * USZ : Qprev + s * USZ;
    int i = s * 2 + LAYER;
    gemm_body<true>(A, ctxb + s * USZ,
                    minus_w + (long)i * 2 * DIM * DIM,
                    Wb + (long)i * DIM * DIM,
                    DIM, tmpb + s * USZ, 2 * DIM, DIM, DIM, DIM, dynsm);
}

// pad a [4096,205]->[4096,224] and wa [205,512]->[224,512] (zero fill)
__global__ void pad_a_kernel(
    const float* __restrict__ a, const float* __restrict__ wa,
    float* __restrict__ pa, float* __restrict__ pwa)
{
    int idx = blockIdx.x * 256 + threadIdx.x;
    const int NA = 4096 * KA_PAD;            // 917504
    const int NB = KA_PAD * DIM;             // 114688
    if (idx < NA) {
        int r = idx / KA_PAD, c = idx - r * KA_PAD;
        pa[idx] = (c < 205) ? a[r * 205 + c] : 0.f;
    } else if (idx < NA + NB) {
        int j = idx - NA;
        int r = j >> 9, c = j & 511;
        pwa[j] = (r < 205) ? wa[r * DIM + c] : 0.f;
    }
}

// ---------------------------------------------------------------------------
// Persistent-K fused attention: one CTA per z (grid 576), 16 q-tiles of 32.
// v2: no max pass (exp2 direct; masked cols underflow to 0 exactly),
// denominator computed redundantly in epilogue from per-warp partial sums.
// Barriers per q-tile: 3 (Qs stage, pre-overlay, post-overlay).
// ---------------------------------------------------------------------------
#define L2E 1.44269504f

template<int LAYER>
__global__ void __launch_bounds__(256, 1) attn_fused(
    const float* __restrict__ Ub, const float* __restrict__ Qprev,
    float* __restrict__ ctxb,
    const float* __restrict__ m0, const float* __restrict__ m1,
    const float* __restrict__ m2, const float* __restrict__ cvec)
{
    extern __shared__ float sm[];
    float* Ks   = sm;                  // 512*68
    float* Qs   = Ks + 512 * 68;       // 32*68
    float* Ps   = Qs + 32 * 68;        // 32*516 (also ctx partial buffer 8*2048)
    float* red  = Ps + 32 * 516;       // 8*32 per-warp row sums

    const int z = blockIdx.x;
    const int s = z >> 6;
    const int bb = (z >> 3) & 7;
    const int hh = z & 7;

    const int tid = threadIdx.x;
    const int w = tid >> 5;
    const int lane = tid & 31;
    const int lr = lane >> 2, lc = lane & 3;

    const int kv = kvi_of(s);
    const float* q0p = Ub + (s / 3) * USZ;
    const float* qin = (LAYER == 0) ? q0p : Qprev + s * USZ;
    const float* kvp = Ub + kv * USZ;
    const float* maskp = ((kv == 0) ? m0 : (kv == 1) ? m1 : m2) + bb * SEQ;

    const float* Qg  = qin + (long)bb * SEQ * DIM + hh * HD;
    const float* Q0g = q0p + (long)bb * SEQ * DIM + hh * HD;
    const float* Kg  = kvp + (long)bb * SEQ * DIM + hh * HD;

    const float SCL = 0.125f * L2E;    // scores scale in log2 domain
    float cv = 0.f, pscale = 1e8f * L2E;
    if (LAYER == 1) { cv = cvec[s * 2 + 1]; pscale = (1.f + cv) * 1e8f * L2E; }

    // ---- stage K (512x64), resident for whole CTA ----
    {
        unsigned ksb = (unsigned)__cvta_generic_to_shared(Ks);
        int r = tid >> 4, c = (tid & 15) << 2;
#pragma unroll
        for (int i = 0; i < 32; i++) {
            int rr = r + i * 16;
            cp16(ksb + (unsigned)(rr * 68 + c) * 4u, Kg + (long)rr * DIM + c);
        }
        asm volatile("cp.async.commit_group;");
        asm volatile("cp.async.wait_group 0;");
    }
    __syncthreads();

    // mask penalties for this warp's score columns (reused across q-tiles)
    const int nbase = w * 64;
    float mpen[8][2];
#pragma unroll
    for (int ni = 0; ni < 8; ni++) {
        mpen[ni][0] = pscale * (1.f - maskp[nbase + ni * 8 + lc * 2]);
        mpen[ni][1] = pscale * (1.f - maskp[nbase + ni * 8 + lc * 2 + 1]);
    }

    for (int qt = 0; qt < 16; qt++) {
        const int row0 = qt * 32;

        // ---- stage Q tile (32x64); layer 1 stages Qeff = Q1 + c*Q0 ----
        if (LAYER == 0) {
            unsigned qsb = (unsigned)__cvta_generic_to_shared(Qs);
#pragma unroll
            for (int i = 0; i < 2; i++) {
                int idx = tid + i * 256;
                int qr = idx >> 4, qc = (idx & 15) << 2;
                cp16(qsb + (unsigned)(qr * 68 + qc) * 4u,
                     Qg + (long)(row0 + qr) * DIM + qc);
            }
            asm volatile("cp.async.commit_group;");
            asm volatile("cp.async.wait_group 0;");
        } else {
#pragma unroll
            for (int i = 0; i < 8; i++) {
                int idx = tid + i * 256;
                int qr = idx >> 6, qc = idx & 63;
                long go = (long)(row0 + qr) * DIM + qc;
                Qs[qr * 68 + qc] = Qg[go] + cv * Q0g[go];
            }
        }
        __syncthreads();   // Qs ready; also orders prev-iter Ps/red reads
                           // before this iter's Ps/red writes

        // ---- scores: warp w owns seq cols [w*64, w*64+64) ----
        float acc[2][8][4] = {};
#pragma unroll
        for (int ks = 0; ks < 8; ks++) {
            unsigned af[2][4];
#pragma unroll
            for (int mi = 0; mi < 2; mi++) {
                const float* q = &Qs[(mi * 16 + lr) * 68 + ks * 8 + lc];
                af[mi][0] = __float_as_uint(q[0]);
                af[mi][1] = __float_as_uint(q[8 * 68]);
                af[mi][2] = __float_as_uint(q[4]);
                af[mi][3] = __float_as_uint(q[8 * 68 + 4]);
            }
#pragma unroll
            for (int ni = 0; ni < 8; ni++) {
                unsigned bf[2];
                const float* kp = &Ks[(nbase + ni * 8 + lr) * 68 + ks * 8 + lc];
                bf[0] = __float_as_uint(kp[0]);
                bf[1] = __float_as_uint(kp[4]);
#pragma unroll
                for (int mi = 0; mi < 2; mi++)
                    MMA_TF32(acc[mi][ni], af[mi], bf);
            }
        }

        // ---- exp2(scale+mask) -> Ps (unnormalized), per-warp row sums ----
#pragma unroll
        for (int i = 0; i < 4; i++) {
            int mi = i >> 1, rr = i & 1;
            int row = mi * 16 + rr * 8 + lr;
            float* prow = &Ps[row * 516 + nbase + lc * 2];
            float sum = 0.f;
#pragma unroll
            for (int ni = 0; ni < 8; ni++) {
                float e0 = exp2f(acc[mi][ni][rr * 2] * SCL - mpen[ni][0]);
                float e1 = exp2f(acc[mi][ni][rr * 2 + 1] * SCL - mpen[ni][1]);
                prow[ni * 8] = e0; prow[ni * 8 + 1] = e1;
                sum += e0 + e1;
            }
            sum += __shfl_xor_sync(0xffffffffu, sum, 1);
            sum += __shfl_xor_sync(0xffffffffu, sum, 2);
            if (lc == 0) red[w * 32 + row] = sum;
        }
        __syncwarp();      // warp-local Ps writes visible to own-warp reads

        // ---- ctx partials: warp w reads ONLY its own Ps cols + Ks ----
        float cacc[2][8][4] = {};
#pragma unroll
        for (int ks = 0; ks < 8; ks++) {
            const int kg = nbase + ks * 8;
            unsigned af[2][4];
#pragma unroll
            for (int mi = 0; mi < 2; mi++) {
                const float* p = &Ps[(mi * 16 + lr) * 516 + kg + lc];
                af[mi][0] = __float_as_uint(p[0]);
                af[mi][1] = __float_as_uint(p[8 * 516]);
                af[mi][2] = __float_as_uint(p[4]);
                af[mi][3] = __float_as_uint(p[8 * 516 + 4]);
            }
#pragma unroll
            for (int ni = 0; ni < 8; ni++) {
                unsigned bf[2];
                const float* kp = &Ks[(kg + lc) * 68 + ni * 8 + lr];
                bf[0] = __float_as_uint(kp[0]);
                bf[1] = __float_as_uint(kp[4 * 68]);
#pragma unroll
                for (int mi = 0; mi < 2; mi++)
                    MMA_TF32(cacc[mi][ni], af[mi], bf);
            }
        }
        __syncthreads();   // all Ps reads done; red visible to all

        // store partials into Ps region, per-row rotated units (no conflicts)
        {
            float* pb = Ps + w * 2048;
#pragma unroll
            for (int mi = 0; mi < 2; mi++)
#pragma unroll
                for (int rr = 0; rr < 2; rr++) {
                    int row = mi * 16 + rr * 8 + lr;
#pragma unroll
                    for (int ni = 0; ni < 8; ni++) {
                        int u = (ni * 4 + lc + row * 4) & 31;
                        *(float2*)&pb[row * 64 + u * 2] =
                            make_float2(cacc[mi][ni][rr * 2],
                                        cacc[mi][ni][rr * 2 + 1]);
                    }
                }
        }
        __syncthreads();

        // reduce 8 partials; denom from red (broadcast LDS); store ctx
        float* ctxg = ctxb + (long)s * USZ + (long)bb * SEQ * DIM
                    + (long)row0 * DIM + hh * HD;
#pragma unroll
        for (int i = 0; i < 4; i++) {
            int idx = tid + i * 256;       // float2 unit over 32x32 units
            int row = idx >> 5;
            int u = idx & 31;
            int up = (u + row * 4) & 31;
            float denom = red[row];
#pragma unroll
            for (int ww = 1; ww < 8; ww++) denom += red[ww * 32 + row];
            float sx = 0.f, sy = 0.f;
#pragma unroll
            for (int ww = 0; ww < 8; ww++) {
                float2 vv = *(float2*)&Ps[ww * 2048 + row * 64 + up * 2];
                sx += vv.x; sy += vv.y;
            }
            float inv = 1.f / denom;
            *(float2*)&ctxg[(long)row * DIM + u * 2] =
                make_float2(sx * inv, sy * inv);
        }
        // next iteration's Qs barrier orders Ps/red reuse
    }
}

// ---------------------------------------------------------------------------
// LayerNorm: warp-per-row, float4 loads, shuffle-only reductions (no BAR).
// 8 rows per CTA. param offset = (row >> 12) * pstride.
// ---------------------------------------------------------------------------
__global__ void __launch_bounds__(256) ln_all(
    const float* __restrict__ X, float* __restrict__ Y,
    const float* __restrict__ g, const float* __restrict__ b, int pstride)
{
    const long row = (long)blockIdx.x * 8 + (threadIdx.x >> 5);
    const int lane = threadIdx.x & 31;
    const int pi = (int)(row >> 12);
    const float* gp = g + (long)pi * pstride;
    const float* bp = b + (long)pi * pstride;
    const float4* x = (const float4*)(X + row * DIM) + lane;
    float4* y = (float4*)(Y + row * DIM) + lane;

    float4 v[4];
#pragma unroll
    for (int i = 0; i < 4; i++) v[i] = x[i * 32];

    float sum = 0.f;
#pragma unroll
    for (int i = 0; i < 4; i++)
        sum += v[i].x + v[i].y + v[i].z + v[i].w;
#pragma unroll
    for (int o = 16; o > 0; o >>= 1)
        sum += __shfl_xor_sync(0xffffffffu, sum, o);
    float mu = sum * (1.f / DIM);

    float q = 0.f;
#pragma unroll
    for (int i = 0; i < 4; i++) {
        v[i].x -= mu; v[i].y -= mu; v[i].z -= mu; v[i].w -= mu;
        q += v[i].x * v[i].x + v[i].y * v[i].y
           + v[i].z * v[i].z + v[i].w * v[i].w;
    }
#pragma unroll
    for (int o = 16; o > 0; o >>= 1)
        q += __shfl_xor_sync(0xffffffffu, q, o);
    float rstd = rsqrtf(q * (1.f / DIM) + 1e-5f);

    const float4* g4 = (const float4*)gp + lane;
    const float4* b4 = (const float4*)bp + lane;
#pragma unroll
    for (int i = 0; i < 4; i++) {
        float4 gg = g4[i * 32], bb = b4[i * 32];
        float4 o;
        o.x = v[i].x * rstd * gg.x + bb.x;
        o.y = v[i].y * rstd * gg.y + bb.y;
        o.z = v[i].z * rstd * gg.z + bb.z;
        o.w = v[i].w * rstd * gg.w + bb.w;
        y[i * 32] = o;
    }
}

// ---------------------------------------------------------------------------
// Pooling
// ---------------------------------------------------------------------------
__global__ void pool_init(float* s, float* m, int n)
{
    int i = blockIdx.x * blockDim.x + threadIdx.x;
    if (i < n) { s[i] = 0.f; m[i] = -INFINITY; }
}

__device__ __forceinline__ void atomicMaxF(float* addr, float val)
{
    int old = __float_as_int(*addr);
    while (__int_as_float(old) < val) {
        int assumed = old;
        old = atomicCAS((int*)addr, assumed, __float_as_int(val));
        if (old == assumed) break;
    }
}

// grid (16, 3 slots, 4 row-chunks); slot g <- streams {g, g+3, g+6}
__global__ void __launch_bounds__(256) pool_b(
    const float* __restrict__ Qb, float* __restrict__ sum,
    float* __restrict__ mx, int layer)
{
    int idx = blockIdx.x * 256 + threadIdx.x;   // (b,d)
    int bb = idx >> 9, d = idx & 511;
    int g = blockIdx.y;
    int r0 = blockIdx.z * 128;
    float s = 0.f, m = -INFINITY;
#pragma unroll
    for (int t = 0; t < 3; t++) {
        const float* p = Qb + (long)(g + t * 3) * USZ
                       + (long)bb * SEQ * DIM + (long)r0 * DIM + d;
        for (int r = 0; r < 128; r++) {
            float v = p[(long)r * DIM];
            s += v;
            m = fmaxf(m, v);
        }
    }
    int k = g * 2 + layer;
    atomicAdd(&sum[k * 4096 + idx], s);
    atomicMaxF(&mx[k * 4096 + idx], m);
}

// ---------------------------------------------------------------------------
// Classifier
// ---------------------------------------------------------------------------
__global__ void __launch_bounds__(256) clf_kernel(
    const float* __restrict__ sum, const float* __restrict__ mx,
    const float* __restrict__ W, float* __restrict__ out)
{
    int bb = blockIdx.x / 9, cls = blockIdx.x % 9;
    int tid = threadIdx.x;
    float acc = 0.f;
    for (int j = tid; j < 3072; j += 256) {
        int k = j >> 9, d = j & 511;
        float sm = sum[k * 4096 + bb * 512 + d] * (1.f / 1536.f);
        float mv = mx[k * 4096 + bb * 512 + d];
        acc += sm * W[(long)j * 9 + cls] + mv * W[(long)(3072 + j) * 9 + cls];
    }
    __shared__ float red[256];
    red[tid] = acc;
    __syncthreads();
    for (int s = 128; s > 0; s >>= 1) {
        if (tid < s) red[tid] += red[tid + s];
        __syncthreads();
    }
    if (tid == 0) out[bb * 9 + cls] = red[0];
}

// ---------------------------------------------------------------------------
// Host orchestration (single stream; no stream/event creation allowed)
// ---------------------------------------------------------------------------
extern "C" void kernel_launch(void* const* d_in, const int* in_sizes, int n_in,
                              void* d_out, int out_size)
{
    const float* l      = (const float*)d_in[0];
    const float* v      = (const float*)d_in[1];
    const float* a      = (const float*)d_in[2];
    const float* l_mask = (const float*)d_in[3];
    const float* v_mask = (const float*)d_in[4];
    const float* a_mask = (const float*)d_in[5];
    const float* wl     = (const float*)d_in[6];
    const float* wv     = (const float*)d_in[7];
    const float* wa     = (const float*)d_in[8];
    const float* n1_g   = (const float*)d_in[9];
    const float* n1_b   = (const float*)d_in[10];
    const float* proj_w = (const float*)d_in[11];
    const float* minus_w= (const float*)d_in[12];
    const float* n2_g   = (const float*)d_in[13];
    const float* n2_b   = (const float*)d_in[14];
    const float* cvec   = (const float*)d_in[15];
    const float* clf_w  = (const float*)d_in[16];
    float* out          = (float*)d_out;

    float *pU, *pqA, *pqB, *pctx, *ptmp, *pW, *psum, *pmax;
    cudaGetSymbolAddress((void**)&pU, g_U);
    cudaGetSymbolAddress((void**)&pqA, g_qA);
    cudaGetSymbolAddress((void**)&pqB, g_qB);
    cudaGetSymbolAddress((void**)&pctx, g_ctx);
    cudaGetSymbolAddress((void**)&ptmp, g_tmp);
    cudaGetSymbolAddress((void**)&pW, g_W);
    cudaGetSymbolAddress((void**)&psum, g_sum);
    cudaGetSymbolAddress((void**)&pmax, g_max);

    // prologue pad scratch lives in g_ctx (free until attention)
    float* pad_a = pctx;
    float* pad_wa = pctx + 4096 * KA_PAD;

    const int SMEM_ATTN = (512 * 68 + 32 * 68 + 32 * 516 + 256) * 4;
    cudaFuncSetAttribute(attn_fused<0>,
        cudaFuncAttributeMaxDynamicSharedMemorySize, SMEM_ATTN);
    cudaFuncSetAttribute(attn_fused<1>,
        cudaFuncAttributeMaxDynamicSharedMemorySize, SMEM_ATTN);
    cudaFuncSetAttribute(prol_b,
        cudaFuncAttributeMaxDynamicSharedMemorySize, GEMM_SMEM);
    cudaFuncSetAttribute(minus_b<0>,
        cudaFuncAttributeMaxDynamicSharedMemorySize, GEMM_SMEM);
    cudaFuncSetAttribute(minus_b<1>,
        cudaFuncAttributeMaxDynamicSharedMemorySize, GEMM_SMEM);

    pool_init<<<96, 256>>>(psum, pmax, 6 * BATCH * DIM);

    // pad a + wa into scratch
    pad_a_kernel<<<4032, 256>>>(a, wa, pad_a, pad_wa);

    // --- combined prologue: unify l/v/a + W precompute in ONE launch ---
    prol_b<<<dim3(4, 16, 21), 256, GEMM_SMEM>>>(
        l, v, pad_a, wl, wv, pad_wa, ptmp, proj_w, minus_w, pW);
    ln_all<<<3 * 512, 256>>>(ptmp, pU, n1_g, n1_b, 0);

    // --- layer 0 (all 9 streams batched) ---
    attn_fused<0><<<576, 256, SMEM_ATTN>>>(
        pU, nullptr, pctx, l_mask, v_mask, a_mask, cvec);
    minus_b<0><<<dim3(4, 16, 9), 256, GEMM_SMEM>>>(
        pU, nullptr, pctx, minus_w, pW, ptmp);
    ln_all<<<9 * 512, 256>>>(ptmp, pqA, n2_g, n2_b, 2 * DIM);
    pool_b<<<dim3(16, 3, 4), 256>>>(pqA, psum, pmax, 0);

    // --- layer 1 ---
    attn_fused<1><<<576, 256, SMEM_ATTN>>>(
        pU, pqA, pctx, l_mask, v_mask, a_mask, cvec);
    minus_b<1><<<dim3(4, 16, 9), 256, GEMM_SMEM>>>(
        pU, pqA, pctx, minus_w, pW, ptmp);
    ln_all<<<9 * 512, 256>>>(ptmp, pqB, n2_g + DIM, n2_b + DIM, 2 * DIM);
    pool_b<<<dim3(16, 3, 4), 256>>>(pqB, psum, pmax, 1);

    clf_kernel<<<BATCH * 9, 256>>>(psum, pmax, clf_w, out);
}

// round 14
// speedup vs baseline: 1.1631x; 1.0432x over previous
#include <cuda_runtime.h>
#include <math.h>

// ---------------------------------------------------------------------------
// Problem constants
// ---------------------------------------------------------------------------
#define BATCH 8
#define NH 8
#define SEQ 512
#define DIM 512
#define HD 64
#define USZ ((long)BATCH * SEQ * DIM)       // 2097152 floats per stream buffer
#define KA_PAD 224                          // a-modality K padded to 32

// gemm dynamic smem: As 3*256*36 + Bs 3*32*136 floats = 162816 bytes
#define GEMM_SMEM ((3 * 9216 + 3 * 4352) * 4)

// ---------------------------------------------------------------------------
// Scratch (device globals; no allocations allowed)
// ---------------------------------------------------------------------------
__device__ float g_U[3 * 2097152];          // unified l,v,a
__device__ float g_qA[9 * 2097152];         // layer-0 outputs per stream
__device__ float g_qB[9 * 2097152];         // layer-1 outputs per stream
__device__ float g_ctx[9 * 2097152];        // ctx; also prologue pad scratch
__device__ float g_tmp[9 * 2097152];
__device__ float g_W[18 * DIM * DIM];       // proj @ minus_bottom
__device__ float g_sum[6 * BATCH * DIM];
__device__ float g_max[6 * BATCH * DIM];

// ---------------------------------------------------------------------------
// MMA / cp.async helpers
// ---------------------------------------------------------------------------
#define MMA_TF32(d, a, b)                                                     \
    asm volatile(                                                             \
        "mma.sync.aligned.m16n8k8.row.col.f32.tf32.tf32.f32 "                 \
        "{%0,%1,%2,%3},{%4,%5,%6,%7},{%8,%9},{%0,%1,%2,%3};"                  \
        : "+f"(d[0]), "+f"(d[1]), "+f"(d[2]), "+f"(d[3])                      \
        : "r"(a[0]), "r"(a[1]), "r"(a[2]), "r"(a[3]), "r"(b[0]), "r"(b[1]))

__device__ __forceinline__ void cp16(unsigned dst, const float* src)
{
    asm volatile("cp.async.cg.shared.global [%0], [%1], 16;"
                 :: "r"(dst), "l"(src));
}

// stream tables: qsrc[s] = s/3 ; kvi[s] via 2-bit packed code {0,1,2,1,0,2,2,0,1}
__device__ __forceinline__ int kvi_of(int s) { return (75876 >> (2 * s)) & 3; }

// ---------------------------------------------------------------------------
// Shared GEMM body (verified round-13): NN, CTA tile 256x128x32, 3-stage.
// ---------------------------------------------------------------------------
template<bool SPLIT>
__device__ __forceinline__ void gemm_body(
    const float* __restrict__ A, const float* __restrict__ A2,
    const float* __restrict__ B, const float* __restrict__ B2,
    int Ksplit, float* __restrict__ C,
    int K, int lda, int ldb, int ldc, float* sm)
{
    float* As = sm;                 // 3 * 9216
    float* Bs = sm + 3 * 9216;      // 3 * 4352

    const int tid = threadIdx.x;
    const int bm = blockIdx.y * 256;
    const int bn = blockIdx.x * 128;
    const int warp = tid >> 5;
    const int warpm = warp & 3, warpn = warp >> 2;
    const int lane = tid & 31;
    const int lr = lane >> 2, lc = lane & 3;
    const int nT = K >> 5;

    const int ar = tid >> 2;
    const int aj = (tid & 3) << 2;
    const long aoff0 = (long)(bm + ar) * lda + aj;
    const long aoff1 = (long)(bm + ar + 64) * lda + aj;
    const long aoff2 = (long)(bm + ar + 128) * lda + aj;
    const long aoff3 = (long)(bm + ar + 192) * lda + aj;
    const int brow = tid >> 4;
    const long boffg = (long)brow * ldb + bn + ((tid & 15) << 3);

    const unsigned asb = (unsigned)__cvta_generic_to_shared(As);
    const unsigned bsb = (unsigned)__cvta_generic_to_shared(Bs);
    const unsigned sa0 = asb + (unsigned)(ar * 36 + aj) * 4u;
    const unsigned sa1 = sa0 + 64u * 36u * 4u;
    const unsigned sa2 = sa0 + 128u * 36u * 4u;
    const unsigned sa3 = sa0 + 192u * 36u * 4u;
    const unsigned sb0 = bsb + (unsigned)(brow * 136 + ((tid & 15) << 3)) * 4u;

    auto load_tile = [&](int t, int st) {
        int k0 = t << 5;
        const float* Ab = A; const float* Bb = B; int kk = k0;
        if (SPLIT && k0 >= Ksplit) { Ab = A2; Bb = B2; kk = k0 - Ksplit; }
        unsigned oa = (unsigned)st * (9216 * 4u);
        unsigned ob = (unsigned)st * (4352 * 4u);
        cp16(sa0 + oa, Ab + aoff0 + kk);
        cp16(sa0 + oa + 64u, Ab + aoff0 + kk + 16);
        cp16(sa1 + oa, Ab + aoff1 + kk);
        cp16(sa1 + oa + 64u, Ab + aoff1 + kk + 16);
        cp16(sa2 + oa, Ab + aoff2 + kk);
        cp16(sa2 + oa + 64u, Ab + aoff2 + kk + 16);
        cp16(sa3 + oa, Ab + aoff3 + kk);
        cp16(sa3 + oa + 64u, Ab + aoff3 + kk + 16);
        const float* bp = Bb + (long)kk * ldb + boffg;
        cp16(sb0 + ob, bp);
        cp16(sb0 + ob + 16u, bp + 4);
        const float* bp2 = bp + 16 * ldb;
        cp16(sb0 + ob + 16u * 136u * 4u, bp2);
        cp16(sb0 + ob + 16u * 136u * 4u + 16u, bp2 + 4);
    };

#pragma unroll
    for (int st = 0; st < 2; st++) {
        if (st < nT) load_tile(st, st);
        asm volatile("cp.async.commit_group;");
    }

    float acc[4][8][4] = {};
    const int afb = (warpm * 64 + lr) * 36 + lc;
    const int bfb = lc * 136 + warpn * 64 + lr;

    for (int t = 0; t < nT; t++) {
        asm volatile("cp.async.wait_group 1;");
        __syncthreads();
        if (t + 2 < nT) load_tile(t + 2, (t + 2) % 3);
        asm volatile("cp.async.commit_group;");

        const float* as = As + (t % 3) * 9216;
        const float* bs = Bs + (t % 3) * 4352;
#pragma unroll
        for (int ks = 0; ks < 4; ks++) {
            unsigned af[4][4];
#pragma unroll
            for (int mi = 0; mi < 4; mi++) {
                int base = afb + mi * 576 + ks * 8;
                af[mi][0] = __float_as_uint(as[base]);
                af[mi][1] = __float_as_uint(as[base + 288]);
                af[mi][2] = __float_as_uint(as[base + 4]);
                af[mi][3] = __float_as_uint(as[base + 292]);
            }
            unsigned bf[8][2];
#pragma unroll
            for (int ni = 0; ni < 8; ni++) {
                int base = bfb + ni * 8 + ks * 1088;
                bf[ni][0] = __float_as_uint(bs[base]);
                bf[ni][1] = __float_as_uint(bs[base + 544]);
            }
#pragma unroll
            for (int mi = 0; mi < 4; mi++)
#pragma unroll
                for (int ni = 0; ni < 8; ni++)
                    MMA_TF32(acc[mi][ni], af[mi], bf[ni]);
        }
    }

#pragma unroll
    for (int mi = 0; mi < 4; mi++)
#pragma unroll
        for (int ni = 0; ni < 8; ni++) {
            int row0 = bm + warpm * 64 + mi * 16 + lr;
            int col = bn + warpn * 64 + ni * 8 + lc * 2;
#pragma unroll
            for (int rr = 0; rr < 2; rr++) {
                int row = row0 + rr * 8;
                *(float2*)&C[(long)row * ldc + col] =
                    make_float2(acc[mi][ni][rr * 2], acc[mi][ni][rr * 2 + 1]);
            }
        }
}

// combined prologue: z 0..2 = unify (l K=768, v K=640, padded-a K=224),
// z 3..20 = W[i] = proj_w[i] @ minus_w[i][512:1024] (i = z-3, y<2 only)
__global__ void __launch_bounds__(256) prol_b(
    const float* __restrict__ l, const float* __restrict__ v,
    const float* __restrict__ pa,
    const float* __restrict__ wl, const float* __restrict__ wv,
    const float* __restrict__ pwa, float* __restrict__ tmpb,
    const float* __restrict__ proj_w, const float* __restrict__ minus_w,
    float* __restrict__ Wb)
{
    extern __shared__ float dynsm[];
    int z = blockIdx.z;
    if (z < 3) {
        const float* A; const float* B; int K;
        if (z == 0)      { A = l;  B = wl;  K = 768; }
        else if (z == 1) { A = v;  B = wv;  K = 640; }
        else             { A = pa; B = pwa; K = KA_PAD; }
        gemm_body<false>(A, nullptr, B, nullptr, 0,
                         tmpb + (long)z * USZ, K, K, DIM, DIM, dynsm);
    } else {
        if (blockIdx.y >= 2) return;
        int i = z - 3;
        gemm_body<false>(proj_w + (long)i * DIM * DIM, nullptr,
                         minus_w + (long)i * 2 * DIM * DIM + (long)DIM * DIM,
                         nullptr, 0,
                         Wb + (long)i * DIM * DIM, DIM, DIM, DIM, DIM, dynsm);
    }
}

// batched minus GEMM: tmp[s] = qin[s] @ minus_top[i] + ctx[s] @ W[i], i=s*2+L
template<int LAYER>
__global__ void __launch_bounds__(256) minus_b(
    const float* __restrict__ Ub, const float* __restrict__ Qprev,
    const float* __restrict__ ctxb, const float* __restrict__ minus_w,
    const float* __restrict__ Wb, float* __restrict__ tmpb)
{
    extern __shared__ float dynsm[];
    int s = blockIdx.z;
    const float* A = (LAYER == 0) ? Ub + (s / 3) * USZ : Qprev + s * USZ;
    int i = s * 2 + LAYER;
    gemm_body<true>(A, ctxb + s * USZ,
                    minus_w + (long)i * 2 * DIM * DIM,
                    Wb + (long)i * DIM * DIM,
                    DIM, tmpb + s * USZ, 2 * DIM, DIM, DIM, DIM, dynsm);
}

// pad a [4096,205]->[4096,224] and wa [205,512]->[224,512] (zero fill)
__global__ void pad_a_kernel(
    const float* __restrict__ a, const float* __restrict__ wa,
    float* __restrict__ pa, float* __restrict__ pwa)
{
    int idx = blockIdx.x * 256 + threadIdx.x;
    const int NA = 4096 * KA_PAD;            // 917504
    const int NB = KA_PAD * DIM;             // 114688
    if (idx < NA) {
        int r = idx / KA_PAD, c = idx - r * KA_PAD;
        pa[idx] = (c < 205) ? a[r * 205 + c] : 0.f;
    } else if (idx < NA + NB) {
        int j = idx - NA;
        int r = j >> 9, c = j & 511;
        pwa[j] = (r < 205) ? wa[r * DIM + c] : 0.f;
    }
}

// ---------------------------------------------------------------------------
// Persistent-K fused attention (round-13 v2 + double-buffered Q staging).
// One CTA per z (grid 576), 16 q-tiles of 32. No max pass; denominator from
// per-warp partial sums. Next q-tile's Q is staged right after the scores
// phase (cp.async for L0, direct Qeff stores for L1) and consumed after the
// next top-of-loop barrier.
// ---------------------------------------------------------------------------
#define L2E 1.44269504f

template<int LAYER>
__global__ void __launch_bounds__(256, 1) attn_fused(
    const float* __restrict__ Ub, const float* __restrict__ Qprev,
    float* __restrict__ ctxb,
    const float* __restrict__ m0, const float* __restrict__ m1,
    const float* __restrict__ m2, const float* __restrict__ cvec)
{
    extern __shared__ float sm[];
    float* Ks   = sm;                  // 512*68
    float* Qs0  = Ks + 512 * 68;       // 32*68
    float* Qs1  = Qs0 + 2176;          // 32*68
    float* Ps   = Qs0 + 4352;          // 32*516 (also ctx partial buffer 8*2048)
    float* red  = Ps + 32 * 516;       // 8*32 per-warp row sums

    const int z = blockIdx.x;
    const int s = z >> 6;
    const int bb = (z >> 3) & 7;
    const int hh = z & 7;

    const int tid = threadIdx.x;
    const int w = tid >> 5;
    const int lane = tid & 31;
    const int lr = lane >> 2, lc = lane & 3;

    const int kv = kvi_of(s);
    const float* q0p = Ub + (s / 3) * USZ;
    const float* qin = (LAYER == 0) ? q0p : Qprev + s * USZ;
    const float* kvp = Ub + kv * USZ;
    const float* maskp = ((kv == 0) ? m0 : (kv == 1) ? m1 : m2) + bb * SEQ;

    const float* Qg  = qin + (long)bb * SEQ * DIM + hh * HD;
    const float* Q0g = q0p + (long)bb * SEQ * DIM + hh * HD;
    const float* Kg  = kvp + (long)bb * SEQ * DIM + hh * HD;

    const float SCL = 0.125f * L2E;    // scores scale in log2 domain
    float cv = 0.f, pscale = 1e8f * L2E;
    if (LAYER == 1) { cv = cvec[s * 2 + 1]; pscale = (1.f + cv) * 1e8f * L2E; }

    // ---- stage K (512x64), resident for whole CTA ----
    {
        unsigned ksb = (unsigned)__cvta_generic_to_shared(Ks);
        int r = tid >> 4, c = (tid & 15) << 2;
#pragma unroll
        for (int i = 0; i < 32; i++) {
            int rr = r + i * 16;
            cp16(ksb + (unsigned)(rr * 68 + c) * 4u, Kg + (long)rr * DIM + c);
        }
        asm volatile("cp.async.commit_group;");
    }

    // mask penalties for this warp's score columns (reused across q-tiles)
    const int nbase = w * 64;
    float mpen[8][2];
#pragma unroll
    for (int ni = 0; ni < 8; ni++) {
        mpen[ni][0] = pscale * (1.f - maskp[nbase + ni * 8 + lc * 2]);
        mpen[ni][1] = pscale * (1.f - maskp[nbase + ni * 8 + lc * 2 + 1]);
    }

    // stage Q tile qt into buffer qb (async for L0, direct for L1)
    auto stage_q = [&](int qt, float* qb) {
        const int r0 = qt * 32;
        if (LAYER == 0) {
            unsigned qsb = (unsigned)__cvta_generic_to_shared(qb);
#pragma unroll
            for (int i = 0; i < 2; i++) {
                int idx = tid + i * 256;
                int qr = idx >> 4, qc = (idx & 15) << 2;
                cp16(qsb + (unsigned)(qr * 68 + qc) * 4u,
                     Qg + (long)(r0 + qr) * DIM + qc);
            }
            asm volatile("cp.async.commit_group;");
        } else {
#pragma unroll
            for (int i = 0; i < 8; i++) {
                int idx = tid + i * 256;
                int qr = idx >> 6, qc = idx & 63;
                long go = (long)(r0 + qr) * DIM + qc;
                qb[qr * 68 + qc] = Qg[go] + cv * Q0g[go];
            }
        }
    };

    // prologue: stage q-tile 0 (K group + Q group both outstanding for L0)
    stage_q(0, Qs0);
    asm volatile("cp.async.wait_group 0;");   // K + Q0 ready (L0); K ready (L1)
    __syncthreads();

    for (int qt = 0; qt < 16; qt++) {
        const int row0 = qt * 32;
        float* qcur = (qt & 1) ? Qs1 : Qs0;
        float* qnext = (qt & 1) ? Qs0 : Qs1;

        // ---- scores: warp w owns seq cols [w*64, w*64+64) ----
        float acc[2][8][4] = {};
#pragma unroll
        for (int ks = 0; ks < 8; ks++) {
            unsigned af[2][4];
#pragma unroll
            for (int mi = 0; mi < 2; mi++) {
                const float* q = &qcur[(mi * 16 + lr) * 68 + ks * 8 + lc];
                af[mi][0] = __float_as_uint(q[0]);
                af[mi][1] = __float_as_uint(q[8 * 68]);
                af[mi][2] = __float_as_uint(q[4]);
                af[mi][3] = __float_as_uint(q[8 * 68 + 4]);
            }
#pragma unroll
            for (int ni = 0; ni < 8; ni++) {
                unsigned bf[2];
                const float* kp = &Ks[(nbase + ni * 8 + lr) * 68 + ks * 8 + lc];
                bf[0] = __float_as_uint(kp[0]);
                bf[1] = __float_as_uint(kp[4]);
#pragma unroll
                for (int mi = 0; mi < 2; mi++)
                    MMA_TF32(acc[mi][ni], af[mi], bf);
            }
        }

        // ---- prefetch next Q tile into the other buffer ----
        if (qt + 1 < 16) stage_q(qt + 1, qnext);

        // ---- exp2(scale+mask) -> Ps (unnormalized), per-warp row sums ----
#pragma unroll
        for (int i = 0; i < 4; i++) {
            int mi = i >> 1, rr = i & 1;
            int row = mi * 16 + rr * 8 + lr;
            float* prow = &Ps[row * 516 + nbase + lc * 2];
            float sum = 0.f;
#pragma unroll
            for (int ni = 0; ni < 8; ni++) {
                float e0 = exp2f(acc[mi][ni][rr * 2] * SCL - mpen[ni][0]);
                float e1 = exp2f(acc[mi][ni][rr * 2 + 1] * SCL - mpen[ni][1]);
                prow[ni * 8] = e0; prow[ni * 8 + 1] = e1;
                sum += e0 + e1;
            }
            sum += __shfl_xor_sync(0xffffffffu, sum, 1);
            sum += __shfl_xor_sync(0xffffffffu, sum, 2);
            if (lc == 0) red[w * 32 + row] = sum;
        }
        __syncwarp();      // warp-local Ps writes visible to own-warp reads

        // ---- ctx partials: warp w reads ONLY its own Ps cols + Ks ----
        float cacc[2][8][4] = {};
#pragma unroll
        for (int ks = 0; ks < 8; ks++) {
            const int kg = nbase + ks * 8;
            unsigned af[2][4];
#pragma unroll
            for (int mi = 0; mi < 2; mi++) {
                const float* p = &Ps[(mi * 16 + lr) * 516 + kg + lc];
                af[mi][0] = __float_as_uint(p[0]);
                af[mi][1] = __float_as_uint(p[8 * 516]);
                af[mi][2] = __float_as_uint(p[4]);
                af[mi][3] = __float_as_uint(p[8 * 516 + 4]);
            }
#pragma unroll
            for (int ni = 0; ni < 8; ni++) {
                unsigned bf[2];
                const float* kp = &Ks[(kg + lc) * 68 + ni * 8 + lr];
                bf[0] = __float_as_uint(kp[0]);
                bf[1] = __float_as_uint(kp[4 * 68]);
#pragma unroll
                for (int mi = 0; mi < 2; mi++)
                    MMA_TF32(cacc[mi][ni], af[mi], bf);
            }
        }
        __syncthreads();   // all Ps reads done; red visible to all

        // store partials into Ps region, per-row rotated units (no conflicts)
        {
            float* pb = Ps + w * 2048;
#pragma unroll
            for (int mi = 0; mi < 2; mi++)
#pragma unroll
                for (int rr = 0; rr < 2; rr++) {
                    int row = mi * 16 + rr * 8 + lr;
#pragma unroll
                    for (int ni = 0; ni < 8; ni++) {
                        int u = (ni * 4 + lc + row * 4) & 31;
                        *(float2*)&pb[row * 64 + u * 2] =
                            make_float2(cacc[mi][ni][rr * 2],
                                        cacc[mi][ni][rr * 2 + 1]);
                    }
                }
        }
        __syncthreads();

        // reduce 8 partials; denom from red (broadcast LDS); store ctx
        float* ctxg = ctxb + (long)s * USZ + (long)bb * SEQ * DIM
                    + (long)row0 * DIM + hh * HD;
#pragma unroll
        for (int i = 0; i < 4; i++) {
            int idx = tid + i * 256;       // float2 unit over 32x32 units
            int row = idx >> 5;
            int u = idx & 31;
            int up = (u + row * 4) & 31;
            float denom = red[row];
#pragma unroll
            for (int ww = 1; ww < 8; ww++) denom += red[ww * 32 + row];
            float sx = 0.f, sy = 0.f;
#pragma unroll
            for (int ww = 0; ww < 8; ww++) {
                float2 vv = *(float2*)&Ps[ww * 2048 + row * 64 + up * 2];
                sx += vv.x; sy += vv.y;
            }
            float inv = 1.f / denom;
            *(float2*)&ctxg[(long)row * DIM + u * 2] =
                make_float2(sx * inv, sy * inv);
        }

        // top-of-next-iteration sync: orders Ps/red reuse AND publishes qnext
        if (qt + 1 < 16) {
            if (LAYER == 0) asm volatile("cp.async.wait_group 0;");
            __syncthreads();
        }
    }
}

// ---------------------------------------------------------------------------
// LayerNorm: warp-per-row, float4 loads, shuffle-only reductions.
// 8 rows per CTA (all same stream & batch when rows%512 aligned).
// POOL=1: fuse mean/max pooling — CTA-local cross-warp reduction in smem,
// then one atomicAdd + one atomicMaxF per (col) per CTA.
// param offset = (row >> 12) * pstride; slot k = ((row>>12)%3)*2 + layer.
// ---------------------------------------------------------------------------
__device__ __forceinline__ void atomicMaxF(float* addr, float val)
{
    int old = __float_as_int(*addr);
    while (__int_as_float(old) < val) {
        int assumed = old;
        old = atomicCAS((int*)addr, assumed, __float_as_int(val));
        if (old == assumed) break;
    }
}

template<int POOL>
__global__ void __launch_bounds__(256) ln_all(
    const float* __restrict__ X, float* __restrict__ Y,
    const float* __restrict__ g, const float* __restrict__ b, int pstride,
    float* __restrict__ gsum, float* __restrict__ gmax, int layer)
{
    __shared__ float sb[8 * 512];

    const long row = (long)blockIdx.x * 8 + (threadIdx.x >> 5);
    const int wid = threadIdx.x >> 5;
    const int lane = threadIdx.x & 31;
    const int pi = (int)(row >> 12);
    const float* gp = g + (long)pi * pstride;
    const float* bp = b + (long)pi * pstride;
    const float4* x = (const float4*)(X + row * DIM) + lane;
    float4* y = (float4*)(Y + row * DIM) + lane;

    float4 v[4];
#pragma unroll
    for (int i = 0; i < 4; i++) v[i] = x[i * 32];

    float sum = 0.f;
#pragma unroll
    for (int i = 0; i < 4; i++)
        sum += v[i].x + v[i].y + v[i].z + v[i].w;
#pragma unroll
    for (int o = 16; o > 0; o >>= 1)
        sum += __shfl_xor_sync(0xffffffffu, sum, o);
    float mu = sum * (1.f / DIM);

    float q = 0.f;
#pragma unroll
    for (int i = 0; i < 4; i++) {
        v[i].x -= mu; v[i].y -= mu; v[i].z -= mu; v[i].w -= mu;
        q += v[i].x * v[i].x + v[i].y * v[i].y
           + v[i].z * v[i].z + v[i].w * v[i].w;
    }
#pragma unroll
    for (int o = 16; o > 0; o >>= 1)
        q += __shfl_xor_sync(0xffffffffu, q, o);
    float rstd = rsqrtf(q * (1.f / DIM) + 1e-5f);

    const float4* g4 = (const float4*)gp + lane;
    const float4* b4 = (const float4*)bp + lane;
#pragma unroll
    for (int i = 0; i < 4; i++) {
        float4 gg = g4[i * 32], bb = b4[i * 32];
        float4 o;
        o.x = v[i].x * rstd * gg.x + bb.x;
        o.y = v[i].y * rstd * gg.y + bb.y;
        o.z = v[i].z * rstd * gg.z + bb.z;
        o.w = v[i].w * rstd * gg.w + bb.w;
        y[i * 32] = o;
        if (POOL)
            *(float4*)&sb[wid * 512 + lane * 4 + i * 128] = o;
    }

    if (POOL) {
        __syncthreads();
        const int s = pi;
        const int bb = (int)((row >> 9) & 7);
        const int k = (s % 3) * 2 + layer;
        float* gs = gsum + k * 4096 + bb * 512;
        float* gm = gmax + k * 4096 + bb * 512;
#pragma unroll
        for (int i = 0; i < 2; i++) {
            int c = threadIdx.x + i * 256;
            float ss = 0.f, mm = -INFINITY;
#pragma unroll
            for (int ww = 0; ww < 8; ww++) {
                float vv = sb[ww * 512 + c];
                ss += vv;
                mm = fmaxf(mm, vv);
            }
            atomicAdd(&gs[c], ss);
            atomicMaxF(&gm[c], mm);
        }
    }
}

// ---------------------------------------------------------------------------
// Pooling init
// ---------------------------------------------------------------------------
__global__ void pool_init(float* s, float* m, int n)
{
    int i = blockIdx.x * blockDim.x + threadIdx.x;
    if (i < n) { s[i] = 0.f; m[i] = -INFINITY; }
}

// ---------------------------------------------------------------------------
// Classifier
// ---------------------------------------------------------------------------
__global__ void __launch_bounds__(256) clf_kernel(
    const float* __restrict__ sum, const float* __restrict__ mx,
    const float* __restrict__ W, float* __restrict__ out)
{
    int bb = blockIdx.x / 9, cls = blockIdx.x % 9;
    int tid = threadIdx.x;
    float acc = 0.f;
    for (int j = tid; j < 3072; j += 256) {
        int k = j >> 9, d = j & 511;
        float sm = sum[k * 4096 + bb * 512 + d] * (1.f / 1536.f);
        float mv = mx[k * 4096 + bb * 512 + d];
        acc += sm * W[(long)j * 9 + cls] + mv * W[(long)(3072 + j) * 9 + cls];
    }
    __shared__ float red[256];
    red[tid] = acc;
    __syncthreads();
    for (int s = 128; s > 0; s >>= 1) {
        if (tid < s) red[tid] += red[tid + s];
        __syncthreads();
    }
    if (tid == 0) out[bb * 9 + cls] = red[0];
}

// ---------------------------------------------------------------------------
// Host orchestration (single stream; no stream/event creation allowed)
// ---------------------------------------------------------------------------
extern "C" void kernel_launch(void* const* d_in, const int* in_sizes, int n_in,
                              void* d_out, int out_size)
{
    const float* l      = (const float*)d_in[0];
    const float* v      = (const float*)d_in[1];
    const float* a      = (const float*)d_in[2];
    const float* l_mask = (const float*)d_in[3];
    const float* v_mask = (const float*)d_in[4];
    const float* a_mask = (const float*)d_in[5];
    const float* wl     = (const float*)d_in[6];
    const float* wv     = (const float*)d_in[7];
    const float* wa     = (const float*)d_in[8];
    const float* n1_g   = (const float*)d_in[9];
    const float* n1_b   = (const float*)d_in[10];
    const float* proj_w = (const float*)d_in[11];
    const float* minus_w= (const float*)d_in[12];
    const float* n2_g   = (const float*)d_in[13];
    const float* n2_b   = (const float*)d_in[14];
    const float* cvec   = (const float*)d_in[15];
    const float* clf_w  = (const float*)d_in[16];
    float* out          = (float*)d_out;

    float *pU, *pqA, *pqB, *pctx, *ptmp, *pW, *psum, *pmax;
    cudaGetSymbolAddress((void**)&pU, g_U);
    cudaGetSymbolAddress((void**)&pqA, g_qA);
    cudaGetSymbolAddress((void**)&pqB, g_qB);
    cudaGetSymbolAddress((void**)&pctx, g_ctx);
    cudaGetSymbolAddress((void**)&ptmp, g_tmp);
    cudaGetSymbolAddress((void**)&pW, g_W);
    cudaGetSymbolAddress((void**)&psum, g_sum);
    cudaGetSymbolAddress((void**)&pmax, g_max);

    // prologue pad scratch lives in g_ctx (free until attention)
    float* pad_a = pctx;
    float* pad_wa = pctx + 4096 * KA_PAD;

    const int SMEM_ATTN = (512 * 68 + 2 * 2176 + 32 * 516 + 256) * 4;
    cudaFuncSetAttribute(attn_fused<0>,
        cudaFuncAttributeMaxDynamicSharedMemorySize, SMEM_ATTN);
    cudaFuncSetAttribute(attn_fused<1>,
        cudaFuncAttributeMaxDynamicSharedMemorySize, SMEM_ATTN);
    cudaFuncSetAttribute(prol_b,
        cudaFuncAttributeMaxDynamicSharedMemorySize, GEMM_SMEM);
    cudaFuncSetAttribute(minus_b<0>,
        cudaFuncAttributeMaxDynamicSharedMemorySize, GEMM_SMEM);
    cudaFuncSetAttribute(minus_b<1>,
        cudaFuncAttributeMaxDynamicSharedMemorySize, GEMM_SMEM);

    pool_init<<<96, 256>>>(psum, pmax, 6 * BATCH * DIM);

    // pad a + wa into scratch
    pad_a_kernel<<<4032, 256>>>(a, wa, pad_a, pad_wa);

    // --- combined prologue: unify l/v/a + W precompute in ONE launch ---
    prol_b<<<dim3(4, 16, 21), 256, GEMM_SMEM>>>(
        l, v, pad_a, wl, wv, pad_wa, ptmp, proj_w, minus_w, pW);
    ln_all<0><<<3 * 512, 256>>>(ptmp, pU, n1_g, n1_b, 0,
                                nullptr, nullptr, 0);

    // --- layer 0 (all 9 streams batched) ---
    attn_fused<0><<<576, 256, SMEM_ATTN>>>(
        pU, nullptr, pctx, l_mask, v_mask, a_mask, cvec);
    minus_b<0><<<dim3(4, 16, 9), 256, GEMM_SMEM>>>(
        pU, nullptr, pctx, minus_w, pW, ptmp);
    ln_all<1><<<9 * 512, 256>>>(ptmp, pqA, n2_g, n2_b, 2 * DIM,
                                psum, pmax, 0);

    // --- layer 1 ---
    attn_fused<1><<<576, 256, SMEM_ATTN>>>(
        pU, pqA, pctx, l_mask, v_mask, a_mask, cvec);
    minus_b<1><<<dim3(4, 16, 9), 256, GEMM_SMEM>>>(
        pU, pqA, pctx, minus_w, pW, ptmp);
    ln_all<1><<<9 * 512, 256>>>(ptmp, pqB, n2_g + DIM, n2_b + DIM, 2 * DIM,
                                psum, pmax, 1);

    clf_kernel<<<BATCH * 9, 256>>>(psum, pmax, clf_w, out);
}

// round 15
// speedup vs baseline: 1.1704x; 1.0063x over previous
#include <cuda_runtime.h>
#include <math.h>

// ---------------------------------------------------------------------------
// Problem constants
// ---------------------------------------------------------------------------
#define BATCH 8
#define NH 8
#define SEQ 512
#define DIM 512
#define HD 64
#define USZ ((long)BATCH * SEQ * DIM)       // 2097152 floats per stream buffer
#define KA_PAD 224                          // a-modality K padded to 32

// gemm dynamic smem: 4 stages x (As 256*36 + Bs 32*136) floats = 217088 bytes
#define GEMM_SMEM ((4 * 9216 + 4 * 4352) * 4)

// ---------------------------------------------------------------------------
// Scratch (device globals; no allocations allowed)
// ---------------------------------------------------------------------------
__device__ float g_U[3 * 2097152];          // unified l,v,a
__device__ float g_qA[9 * 2097152];         // layer-0 outputs per stream
__device__ float g_qB[9 * 2097152];         // layer-1 outputs per stream
__device__ float g_ctx[9 * 2097152];        // ctx; also prologue pad scratch
__device__ float g_tmp[9 * 2097152];
__device__ float g_W[18 * DIM * DIM];       // proj @ minus_bottom
__device__ float g_sum[6 * BATCH * DIM];
__device__ float g_max[6 * BATCH * DIM];

// ---------------------------------------------------------------------------
// MMA / cp.async helpers
// ---------------------------------------------------------------------------
#define MMA_TF32(d, a, b)                                                     \
    asm volatile(                                                             \
        "mma.sync.aligned.m16n8k8.row.col.f32.tf32.tf32.f32 "                 \
        "{%0,%1,%2,%3},{%4,%5,%6,%7},{%8,%9},{%0,%1,%2,%3};"                  \
        : "+f"(d[0]), "+f"(d[1]), "+f"(d[2]), "+f"(d[3])                      \
        : "r"(a[0]), "r"(a[1]), "r"(a[2]), "r"(a[3]), "r"(b[0]), "r"(b[1]))

__device__ __forceinline__ void cp16(unsigned dst, const float* src)
{
    asm volatile("cp.async.cg.shared.global [%0], [%1], 16;"
                 :: "r"(dst), "l"(src));
}

// stream tables: qsrc[s] = s/3 ; kvi[s] via 2-bit packed code {0,1,2,1,0,2,2,0,1}
__device__ __forceinline__ int kvi_of(int s) { return (75876 >> (2 * s)) & 3; }

// ---------------------------------------------------------------------------
// Shared GEMM body: NN, CTA tile 256x128x32, cp.async 4-stage.
// 8 warps (warpm 0..3 x warpn 0..1), warp tile 64x64.
// K%32==0, lda%4==0, ldb%4==0, 16B-aligned ptrs, M%256==0, N%128==0.
// SPLIT: k >= Ksplit reads A2/B2 (k rebased; Ksplit%32==0).
// ---------------------------------------------------------------------------
template<bool SPLIT>
__device__ __forceinline__ void gemm_body(
    const float* __restrict__ A, const float* __restrict__ A2,
    const float* __restrict__ B, const float* __restrict__ B2,
    int Ksplit, float* __restrict__ C,
    int K, int lda, int ldb, int ldc, float* sm)
{
    float* As = sm;                 // 4 * 9216
    float* Bs = sm + 4 * 9216;      // 4 * 4352

    const int tid = threadIdx.x;
    const int bm = blockIdx.y * 256;
    const int bn = blockIdx.x * 128;
    const int warp = tid >> 5;
    const int warpm = warp & 3, warpn = warp >> 2;
    const int lane = tid & 31;
    const int lr = lane >> 2, lc = lane & 3;
    const int nT = K >> 5;

    const int ar = tid >> 2;
    const int aj = (tid & 3) << 2;
    const long aoff0 = (long)(bm + ar) * lda + aj;
    const long aoff1 = (long)(bm + ar + 64) * lda + aj;
    const long aoff2 = (long)(bm + ar + 128) * lda + aj;
    const long aoff3 = (long)(bm + ar + 192) * lda + aj;
    const int brow = tid >> 4;
    const long boffg = (long)brow * ldb + bn + ((tid & 15) << 3);

    const unsigned asb = (unsigned)__cvta_generic_to_shared(As);
    const unsigned bsb = (unsigned)__cvta_generic_to_shared(Bs);
    const unsigned sa0 = asb + (unsigned)(ar * 36 + aj) * 4u;
    const unsigned sa1 = sa0 + 64u * 36u * 4u;
    const unsigned sa2 = sa0 + 128u * 36u * 4u;
    const unsigned sa3 = sa0 + 192u * 36u * 4u;
    const unsigned sb0 = bsb + (unsigned)(brow * 136 + ((tid & 15) << 3)) * 4u;

    auto load_tile = [&](int t, int st) {
        int k0 = t << 5;
        const float* Ab = A; const float* Bb = B; int kk = k0;
        if (SPLIT && k0 >= Ksplit) { Ab = A2; Bb = B2; kk = k0 - Ksplit; }
        unsigned oa = (unsigned)st * (9216 * 4u);
        unsigned ob = (unsigned)st * (4352 * 4u);
        cp16(sa0 + oa, Ab + aoff0 + kk);
        cp16(sa0 + oa + 64u, Ab + aoff0 + kk + 16);
        cp16(sa1 + oa, Ab + aoff1 + kk);
        cp16(sa1 + oa + 64u, Ab + aoff1 + kk + 16);
        cp16(sa2 + oa, Ab + aoff2 + kk);
        cp16(sa2 + oa + 64u, Ab + aoff2 + kk + 16);
        cp16(sa3 + oa, Ab + aoff3 + kk);
        cp16(sa3 + oa + 64u, Ab + aoff3 + kk + 16);
        const float* bp = Bb + (long)kk * ldb + boffg;
        cp16(sb0 + ob, bp);
        cp16(sb0 + ob + 16u, bp + 4);
        const float* bp2 = bp + 16 * ldb;
        cp16(sb0 + ob + 16u * 136u * 4u, bp2);
        cp16(sb0 + ob + 16u * 136u * 4u + 16u, bp2 + 4);
    };

#pragma unroll
    for (int st = 0; st < 3; st++) {
        if (st < nT) load_tile(st, st);
        asm volatile("cp.async.commit_group;");
    }

    float acc[4][8][4] = {};
    const int afb = (warpm * 64 + lr) * 36 + lc;
    const int bfb = lc * 136 + warpn * 64 + lr;

    for (int t = 0; t < nT; t++) {
        asm volatile("cp.async.wait_group 2;");
        __syncthreads();
        if (t + 3 < nT) load_tile(t + 3, (t + 3) & 3);
        asm volatile("cp.async.commit_group;");

        const float* as = As + (t & 3) * 9216;
        const float* bs = Bs + (t & 3) * 4352;
#pragma unroll
        for (int ks = 0; ks < 4; ks++) {
            unsigned af[4][4];
#pragma unroll
            for (int mi = 0; mi < 4; mi++) {
                int base = afb + mi * 576 + ks * 8;
                af[mi][0] = __float_as_uint(as[base]);
                af[mi][1] = __float_as_uint(as[base + 288]);
                af[mi][2] = __float_as_uint(as[base + 4]);
                af[mi][3] = __float_as_uint(as[base + 292]);
            }
            unsigned bf[8][2];
#pragma unroll
            for (int ni = 0; ni < 8; ni++) {
                int base = bfb + ni * 8 + ks * 1088;
                bf[ni][0] = __float_as_uint(bs[base]);
                bf[ni][1] = __float_as_uint(bs[base + 544]);
            }
#pragma unroll
            for (int mi = 0; mi < 4; mi++)
#pragma unroll
                for (int ni = 0; ni < 8; ni++)
                    MMA_TF32(acc[mi][ni], af[mi], bf[ni]);
        }
    }

#pragma unroll
    for (int mi = 0; mi < 4; mi++)
#pragma unroll
        for (int ni = 0; ni < 8; ni++) {
            int row0 = bm + warpm * 64 + mi * 16 + lr;
            int col = bn + warpn * 64 + ni * 8 + lc * 2;
#pragma unroll
            for (int rr = 0; rr < 2; rr++) {
                int row = row0 + rr * 8;
                *(float2*)&C[(long)row * ldc + col] =
                    make_float2(acc[mi][ni][rr * 2], acc[mi][ni][rr * 2 + 1]);
            }
        }
}

// combined prologue: z 0..2 = unify (l K=768, v K=640, padded-a K=224),
// z 3..20 = W[i] = proj_w[i] @ minus_w[i][512:1024] (i = z-3, y<2 only)
__global__ void __launch_bounds__(256) prol_b(
    const float* __restrict__ l, const float* __restrict__ v,
    const float* __restrict__ pa,
    const float* __restrict__ wl, const float* __restrict__ wv,
    const float* __restrict__ pwa, float* __restrict__ tmpb,
    const float* __restrict__ proj_w, const float* __restrict__ minus_w,
    float* __restrict__ Wb)
{
    extern __shared__ float dynsm[];
    int z = blockIdx.z;
    if (z < 3) {
        const float* A; const float* B; int K;
        if (z == 0)      { A = l;  B = wl;  K = 768; }
        else if (z == 1) { A = v;  B = wv;  K = 640; }
        else             { A = pa; B = pwa; K = KA_PAD; }
        gemm_body<false>(A, nullptr, B, nullptr, 0,
                         tmpb + (long)z * USZ, K, K, DIM, DIM, dynsm);
    } else {
        if (blockIdx.y >= 2) return;
        int i = z - 3;
        gemm_body<false>(proj_w + (long)i * DIM * DIM, nullptr,
                         minus_w + (long)i * 2 * DIM * DIM + (long)DIM * DIM,
                         nullptr, 0,
                         Wb + (long)i * DIM * DIM, DIM, DIM, DIM, DIM, dynsm);
    }
}

// batched minus GEMM: tmp[s] = qin[s] @ minus_top[i] + ctx[s] @ W[i], i=s*2+L
template<int LAYER>
__global__ void __launch_bounds__(256) minus_b(
    const float* __restrict__ Ub, const float* __restrict__ Qprev,
    const float* __restrict__ ctxb, const float* __restrict__ minus_w,
    const float* __restrict__ Wb, float* __restrict__ tmpb)
{
    extern __shared__ float dynsm[];
    int s = blockIdx.z;
    const float* A = (LAYER == 0) ? Ub + (s / 3) * USZ : Qprev + s * USZ;
    int i = s * 2 + LAYER;
    gemm_body<true>(A, ctxb + s * USZ,
                    minus_w + (long)i * 2 * DIM * DIM,
                    Wb + (long)i * DIM * DIM,
                    DIM, tmpb + s * USZ, 2 * DIM, DIM, DIM, DIM, dynsm);
}

// pad a [4096,205]->[4096,224], wa [205,512]->[224,512], and init pools
__global__ void init_pad_kernel(
    const float* __restrict__ a, const float* __restrict__ wa,
    float* __restrict__ pa, float* __restrict__ pwa,
    float* __restrict__ psum, float* __restrict__ pmax)
{
    int idx = blockIdx.x * 256 + threadIdx.x;
    const int NA = 4096 * KA_PAD;            // 917504
    const int NB = KA_PAD * DIM;             // 114688
    if (idx < NA) {
        int r = idx / KA_PAD, c = idx - r * KA_PAD;
        pa[idx] = (c < 205) ? a[r * 205 + c] : 0.f;
    } else if (idx < NA + NB) {
        int j = idx - NA;
        int r = j >> 9, c = j & 511;
        pwa[j] = (r < 205) ? wa[r * DIM + c] : 0.f;
    }
    if (idx < 6 * BATCH * DIM) {
        psum[idx] = 0.f;
        pmax[idx] = -INFINITY;
    }
}

// ---------------------------------------------------------------------------
// Persistent-K fused attention (round-14 verified): one CTA per z (grid 576),
// 16 q-tiles of 32, double-buffered Q staging, no max pass.
// ---------------------------------------------------------------------------
#define L2E 1.44269504f

template<int LAYER>
__global__ void __launch_bounds__(256, 1) attn_fused(
    const float* __restrict__ Ub, const float* __restrict__ Qprev,
    float* __restrict__ ctxb,
    const float* __restrict__ m0, const float* __restrict__ m1,
    const float* __restrict__ m2, const float* __restrict__ cvec)
{
    extern __shared__ float sm[];
    float* Ks   = sm;                  // 512*68
    float* Qs0  = Ks + 512 * 68;       // 32*68
    float* Qs1  = Qs0 + 2176;          // 32*68
    float* Ps   = Qs0 + 4352;          // 32*516 (also ctx partial buffer 8*2048)
    float* red  = Ps + 32 * 516;       // 8*32 per-warp row sums

    const int z = blockIdx.x;
    const int s = z >> 6;
    const int bb = (z >> 3) & 7;
    const int hh = z & 7;

    const int tid = threadIdx.x;
    const int w = tid >> 5;
    const int lane = tid & 31;
    const int lr = lane >> 2, lc = lane & 3;

    const int kv = kvi_of(s);
    const float* q0p = Ub + (s / 3) * USZ;
    const float* qin = (LAYER == 0) ? q0p : Qprev + s * USZ;
    const float* kvp = Ub + kv * USZ;
    const float* maskp = ((kv == 0) ? m0 : (kv == 1) ? m1 : m2) + bb * SEQ;

    const float* Qg  = qin + (long)bb * SEQ * DIM + hh * HD;
    const float* Q0g = q0p + (long)bb * SEQ * DIM + hh * HD;
    const float* Kg  = kvp + (long)bb * SEQ * DIM + hh * HD;

    const float SCL = 0.125f * L2E;    // scores scale in log2 domain
    float cv = 0.f, pscale = 1e8f * L2E;
    if (LAYER == 1) { cv = cvec[s * 2 + 1]; pscale = (1.f + cv) * 1e8f * L2E; }

    // ---- stage K (512x64), resident for whole CTA ----
    {
        unsigned ksb = (unsigned)__cvta_generic_to_shared(Ks);
        int r = tid >> 4, c = (tid & 15) << 2;
#pragma unroll
        for (int i = 0; i < 32; i++) {
            int rr = r + i * 16;
            cp16(ksb + (unsigned)(rr * 68 + c) * 4u, Kg + (long)rr * DIM + c);
        }
        asm volatile("cp.async.commit_group;");
    }

    // mask penalties for this warp's score columns (reused across q-tiles)
    const int nbase = w * 64;
    float mpen[8][2];
#pragma unroll
    for (int ni = 0; ni < 8; ni++) {
        mpen[ni][0] = pscale * (1.f - maskp[nbase + ni * 8 + lc * 2]);
        mpen[ni][1] = pscale * (1.f - maskp[nbase + ni * 8 + lc * 2 + 1]);
    }

    auto stage_q = [&](int qt, float* qb) {
        const int r0 = qt * 32;
        if (LAYER == 0) {
            unsigned qsb = (unsigned)__cvta_generic_to_shared(qb);
#pragma unroll
            for (int i = 0; i < 2; i++) {
                int idx = tid + i * 256;
                int qr = idx >> 4, qc = (idx & 15) << 2;
                cp16(qsb + (unsigned)(qr * 68 + qc) * 4u,
                     Qg + (long)(r0 + qr) * DIM + qc);
            }
            asm volatile("cp.async.commit_group;");
        } else {
#pragma unroll
            for (int i = 0; i < 8; i++) {
                int idx = tid + i * 256;
                int qr = idx >> 6, qc = idx & 63;
                long go = (long)(r0 + qr) * DIM + qc;
                qb[qr * 68 + qc] = Qg[go] + cv * Q0g[go];
            }
        }
    };

    stage_q(0, Qs0);
    asm volatile("cp.async.wait_group 0;");
    __syncthreads();

    for (int qt = 0; qt < 16; qt++) {
        const int row0 = qt * 32;
        float* qcur = (qt & 1) ? Qs1 : Qs0;
        float* qnext = (qt & 1) ? Qs0 : Qs1;

        // ---- scores: warp w owns seq cols [w*64, w*64+64) ----
        float acc[2][8][4] = {};
#pragma unroll
        for (int ks = 0; ks < 8; ks++) {
            unsigned af[2][4];
#pragma unroll
            for (int mi = 0; mi < 2; mi++) {
                const float* q = &qcur[(mi * 16 + lr) * 68 + ks * 8 + lc];
                af[mi][0] = __float_as_uint(q[0]);
                af[mi][1] = __float_as_uint(q[8 * 68]);
                af[mi][2] = __float_as_uint(q[4]);
                af[mi][3] = __float_as_uint(q[8 * 68 + 4]);
            }
#pragma unroll
            for (int ni = 0; ni < 8; ni++) {
                unsigned bf[2];
                const float* kp = &Ks[(nbase + ni * 8 + lr) * 68 + ks * 8 + lc];
                bf[0] = __float_as_uint(kp[0]);
                bf[1] = __float_as_uint(kp[4]);
#pragma unroll
                for (int mi = 0; mi < 2; mi++)
                    MMA_TF32(acc[mi][ni], af[mi], bf);
            }
        }

        // ---- prefetch next Q tile into the other buffer ----
        if (qt + 1 < 16) stage_q(qt + 1, qnext);

        // ---- exp2(scale+mask) -> Ps (unnormalized), per-warp row sums ----
#pragma unroll
        for (int i = 0; i < 4; i++) {
            int mi = i >> 1, rr = i & 1;
            int row = mi * 16 + rr * 8 + lr;
            float* prow = &Ps[row * 516 + nbase + lc * 2];
            float sum = 0.f;
#pragma unroll
            for (int ni = 0; ni < 8; ni++) {
                float e0 = exp2f(acc[mi][ni][rr * 2] * SCL - mpen[ni][0]);
                float e1 = exp2f(acc[mi][ni][rr * 2 + 1] * SCL - mpen[ni][1]);
                prow[ni * 8] = e0; prow[ni * 8 + 1] = e1;
                sum += e0 + e1;
            }
            sum += __shfl_xor_sync(0xffffffffu, sum, 1);
            sum += __shfl_xor_sync(0xffffffffu, sum, 2);
            if (lc == 0) red[w * 32 + row] = sum;
        }
        __syncwarp();

        // ---- ctx partials: warp w reads ONLY its own Ps cols + Ks ----
        float cacc[2][8][4] = {};
#pragma unroll
        for (int ks = 0; ks < 8; ks++) {
            const int kg = nbase + ks * 8;
            unsigned af[2][4];
#pragma unroll
            for (int mi = 0; mi < 2; mi++) {
                const float* p = &Ps[(mi * 16 + lr) * 516 + kg + lc];
                af[mi][0] = __float_as_uint(p[0]);
                af[mi][1] = __float_as_uint(p[8 * 516]);
                af[mi][2] = __float_as_uint(p[4]);
                af[mi][3] = __float_as_uint(p[8 * 516 + 4]);
            }
#pragma unroll
            for (int ni = 0; ni < 8; ni++) {
                unsigned bf[2];
                const float* kp = &Ks[(kg + lc) * 68 + ni * 8 + lr];
                bf[0] = __float_as_uint(kp[0]);
                bf[1] = __float_as_uint(kp[4 * 68]);
#pragma unroll
                for (int mi = 0; mi < 2; mi++)
                    MMA_TF32(cacc[mi][ni], af[mi], bf);
            }
        }
        __syncthreads();   // all Ps reads done; red visible to all

        // store partials into Ps region, per-row rotated units (no conflicts)
        {
            float* pb = Ps + w * 2048;
#pragma unroll
            for (int mi = 0; mi < 2; mi++)
#pragma unroll
                for (int rr = 0; rr < 2; rr++) {
                    int row = mi * 16 + rr * 8 + lr;
#pragma unroll
                    for (int ni = 0; ni < 8; ni++) {
                        int u = (ni * 4 + lc + row * 4) & 31;
                        *(float2*)&pb[row * 64 + u * 2] =
                            make_float2(cacc[mi][ni][rr * 2],
                                        cacc[mi][ni][rr * 2 + 1]);
                    }
                }
        }
        __syncthreads();

        // reduce 8 partials; denom once per row; store ctx
        float* ctxg = ctxb + (long)s * USZ + (long)bb * SEQ * DIM
                    + (long)row0 * DIM + hh * HD;
#pragma unroll
        for (int i = 0; i < 4; i++) {
            int idx = tid + i * 256;       // float2 unit over 32x32 units
            int row = idx >> 5;
            int u = idx & 31;
            int up = (u + row * 4) & 31;
            float denom = red[row];
#pragma unroll
            for (int ww = 1; ww < 8; ww++) denom += red[ww * 32 + row];
            float sx = 0.f, sy = 0.f;
#pragma unroll
            for (int ww = 0; ww < 8; ww++) {
                float2 vv = *(float2*)&Ps[ww * 2048 + row * 64 + up * 2];
                sx += vv.x; sy += vv.y;
            }
            float inv = __frcp_rn(denom);
            *(float2*)&ctxg[(long)row * DIM + u * 2] =
                make_float2(sx * inv, sy * inv);
        }

        if (qt + 1 < 16) {
            if (LAYER == 0) asm volatile("cp.async.wait_group 0;");
            __syncthreads();
        }
    }
}

// ---------------------------------------------------------------------------
// LayerNorm (+ optional fused pooling), warp-per-row, float4, shuffle-only.
// ---------------------------------------------------------------------------
__device__ __forceinline__ void atomicMaxF(float* addr, float val)
{
    int old = __float_as_int(*addr);
    while (__int_as_float(old) < val) {
        int assumed = old;
        old = atomicCAS((int*)addr, assumed, __float_as_int(val));
        if (old == assumed) break;
    }
}

template<int POOL>
__global__ void __launch_bounds__(256) ln_all(
    const float* __restrict__ X, float* __restrict__ Y,
    const float* __restrict__ g, const float* __restrict__ b, int pstride,
    float* __restrict__ gsum, float* __restrict__ gmax, int layer)
{
    __shared__ float sb[8 * 512];

    const long row = (long)blockIdx.x * 8 + (threadIdx.x >> 5);
    const int wid = threadIdx.x >> 5;
    const int lane = threadIdx.x & 31;
    const int pi = (int)(row >> 12);
    const float* gp = g + (long)pi * pstride;
    const float* bp = b + (long)pi * pstride;
    const float4* x = (const float4*)(X + row * DIM) + lane;
    float4* y = (float4*)(Y + row * DIM) + lane;

    float4 v[4];
#pragma unroll
    for (int i = 0; i < 4; i++) v[i] = x[i * 32];

    float sum = 0.f;
#pragma unroll
    for (int i = 0; i < 4; i++)
        sum += v[i].x + v[i].y + v[i].z + v[i].w;
#pragma unroll
    for (int o = 16; o > 0; o >>= 1)
        sum += __shfl_xor_sync(0xffffffffu, sum, o);
    float mu = sum * (1.f / DIM);

    float q = 0.f;
#pragma unroll
    for (int i = 0; i < 4; i++) {
        v[i].x -= mu; v[i].y -= mu; v[i].z -= mu; v[i].w -= mu;
        q += v[i].x * v[i].x + v[i].y * v[i].y
           + v[i].z * v[i].z + v[i].w * v[i].w;
    }
#pragma unroll
    for (int o = 16; o > 0; o >>= 1)
        q += __shfl_xor_sync(0xffffffffu, q, o);
    float rstd = rsqrtf(q * (1.f / DIM) + 1e-5f);

    const float4* g4 = (const float4*)gp + lane;
    const float4* b4 = (const float4*)bp + lane;
#pragma unroll
    for (int i = 0; i < 4; i++) {
        float4 gg = g4[i * 32], bb = b4[i * 32];
        float4 o;
        o.x = v[i].x * rstd * gg.x + bb.x;
        o.y = v[i].y * rstd * gg.y + bb.y;
        o.z = v[i].z * rstd * gg.z + bb.z;
        o.w = v[i].w * rstd * gg.w + bb.w;
        y[i * 32] = o;
        if (POOL)
            *(float4*)&sb[wid * 512 + lane * 4 + i * 128] = o;
    }

    if (POOL) {
        __syncthreads();
        const int s = pi;
        const int bb = (int)((row >> 9) & 7);
        const int k = (s % 3) * 2 + layer;
        float* gs = gsum + k * 4096 + bb * 512;
        float* gm = gmax + k * 4096 + bb * 512;
#pragma unroll
        for (int i = 0; i < 2; i++) {
            int c = threadIdx.x + i * 256;
            float ss = 0.f, mm = -INFINITY;
#pragma unroll
            for (int ww = 0; ww < 8; ww++) {
                float vv = sb[ww * 512 + c];
                ss += vv;
                mm = fmaxf(mm, vv);
            }
            atomicAdd(&gs[c], ss);
            atomicMaxF(&gm[c], mm);
        }
    }
}

// ---------------------------------------------------------------------------
// Classifier
// ---------------------------------------------------------------------------
__global__ void __launch_bounds__(256) clf_kernel(
    const float* __restrict__ sum, const float* __restrict__ mx,
    const float* __restrict__ W, float* __restrict__ out)
{
    int bb = blockIdx.x / 9, cls = blockIdx.x % 9;
    int tid = threadIdx.x;
    float acc = 0.f;
    for (int j = tid; j < 3072; j += 256) {
        int k = j >> 9, d = j & 511;
        float sm = sum[k * 4096 + bb * 512 + d] * (1.f / 1536.f);
        float mv = mx[k * 4096 + bb * 512 + d];
        acc += sm * W[(long)j * 9 + cls] + mv * W[(long)(3072 + j) * 9 + cls];
    }
    __shared__ float red[256];
    red[tid] = acc;
    __syncthreads();
    for (int s = 128; s > 0; s >>= 1) {
        if (tid < s) red[tid] += red[tid + s];
        __syncthreads();
    }
    if (tid == 0) out[bb * 9 + cls] = red[0];
}

// ---------------------------------------------------------------------------
// Host orchestration (single stream; no stream/event creation allowed)
// ---------------------------------------------------------------------------
extern "C" void kernel_launch(void* const* d_in, const int* in_sizes, int n_in,
                              void* d_out, int out_size)
{
    const float* l      = (const float*)d_in[0];
    const float* v      = (const float*)d_in[1];
    const float* a      = (const float*)d_in[2];
    const float* l_mask = (const float*)d_in[3];
    const float* v_mask = (const float*)d_in[4];
    const float* a_mask = (const float*)d_in[5];
    const float* wl     = (const float*)d_in[6];
    const float* wv     = (const float*)d_in[7];
    const float* wa     = (const float*)d_in[8];
    const float* n1_g   = (const float*)d_in[9];
    const float* n1_b   = (const float*)d_in[10];
    const float* proj_w = (const float*)d_in[11];
    const float* minus_w= (const float*)d_in[12];
    const float* n2_g   = (const float*)d_in[13];
    const float* n2_b   = (const float*)d_in[14];
    const float* cvec   = (const float*)d_in[15];
    const float* clf_w  = (const float*)d_in[16];
    float* out          = (float*)d_out;

    float *pU, *pqA, *pqB, *pctx, *ptmp, *pW, *psum, *pmax;
    cudaGetSymbolAddress((void**)&pU, g_U);
    cudaGetSymbolAddress((void**)&pqA, g_qA);
    cudaGetSymbolAddress((void**)&pqB, g_qB);
    cudaGetSymbolAddress((void**)&pctx, g_ctx);
    cudaGetSymbolAddress((void**)&ptmp, g_tmp);
    cudaGetSymbolAddress((void**)&pW, g_W);
    cudaGetSymbolAddress((void**)&psum, g_sum);
    cudaGetSymbolAddress((void**)&pmax, g_max);

    // prologue pad scratch lives in g_ctx (free until attention)
    float* pad_a = pctx;
    float* pad_wa = pctx + 4096 * KA_PAD;

    const int SMEM_ATTN = (512 * 68 + 2 * 2176 + 32 * 516 + 256) * 4;
    cudaFuncSetAttribute(attn_fused<0>,
        cudaFuncAttributeMaxDynamicSharedMemorySize, SMEM_ATTN);
    cudaFuncSetAttribute(attn_fused<1>,
        cudaFuncAttributeMaxDynamicSharedMemorySize, SMEM_ATTN);
    cudaFuncSetAttribute(prol_b,
        cudaFuncAttributeMaxDynamicSharedMemorySize, GEMM_SMEM);
    cudaFuncSetAttribute(minus_b<0>,
        cudaFuncAttributeMaxDynamicSharedMemorySize, GEMM_SMEM);
    cudaFuncSetAttribute(minus_b<1>,
        cudaFuncAttributeMaxDynamicSharedMemorySize, GEMM_SMEM);

    // pad a + wa into scratch and init pools (one launch)
    init_pad_kernel<<<4032, 256>>>(a, wa, pad_a, pad_wa, psum, pmax);

    // --- combined prologue: unify l/v/a + W precompute in ONE launch ---
    prol_b<<<dim3(4, 16, 21), 256, GEMM_SMEM>>>(
        l, v, pad_a, wl, wv, pad_wa, ptmp, proj_w, minus_w, pW);
    ln_all<0><<<3 * 512, 256>>>(ptmp, pU, n1_g, n1_b, 0,
                                nullptr, nullptr, 0);

    // --- layer 0 (all 9 streams batched) ---
    attn_fused<0><<<576, 256, SMEM_ATTN>>>(
        pU, nullptr, pctx, l_mask, v_mask, a_mask, cvec);
    minus_b<0><<<dim3(4, 16, 9), 256, GEMM_SMEM>>>(
        pU, nullptr, pctx, minus_w, pW, ptmp);
    ln_all<1><<<9 * 512, 256>>>(ptmp, pqA, n2_g, n2_b, 2 * DIM,
                                psum, pmax, 0);

    // --- layer 1 ---
    attn_fused<1><<<576, 256, SMEM_ATTN>>>(
        pU, pqA, pctx, l_mask, v_mask, a_mask, cvec);
    minus_b<1><<<dim3(4, 16, 9), 256, GEMM_SMEM>>>(
        pU, pqA, pctx, minus_w, pW, ptmp);
    ln_all<1><<<9 * 512, 256>>>(ptmp, pqB, n2_g + DIM, n2_b + DIM, 2 * DIM,
                                psum, pmax, 1);

    clf_kernel<<<BATCH * 9, 256>>>(psum, pmax, clf_w, out);
}